// round 4
// baseline (speedup 1.0000x reference)
#include <cuda_runtime.h>
#include <math.h>

// Problem constants
#define L_    2
#define B_    2
#define S_    2048
#define D_    768
#define H_    12
#define KVH_  4
#define HD_   64
#define NREP_ 3
#define FF_   3072
#define T_    (B_*S_)          // 4096 tokens
#define HALF_HD_ 32

// ---------------- Scratch (device globals; no allocation allowed) ----------
__device__ float g_x[T_*D_];          // running residual stream
__device__ float g_h[T_*D_];          // normed activations
__device__ float g_q[T_*D_];          // Q  [T, H, HD]
__device__ float g_kbuf[T_*KVH_*HD_]; // K  [T, KVH, HD]
__device__ float g_vbuf[T_*KVH_*HD_]; // V  [T, KVH, HD]
__device__ float g_attn[T_*D_];       // attention output [T, H, HD]
__device__ float g_f0[T_*FF_];        // FFN gate / fused
__device__ float g_f1[T_*FF_];        // FFN up
__device__ float g_sc[(size_t)B_*H_*S_*S_]; // scores/probs (402 MB)
__device__ float g_ct[S_*HALF_HD_];   // rope cos table
__device__ float g_st[S_*HALF_HD_];   // rope sin table

// ---------------- RoPE tables (double precision, tiny) ---------------------
__global__ void rope_table_kernel() {
    int idx = blockIdx.x * blockDim.x + threadIdx.x;
    if (idx >= S_ * HALF_HD_) return;
    int s = idx / HALF_HD_;
    int i = idx % HALF_HD_;
    double freq = exp(-log(10000.0) * (double)(2 * i) / (double)HD_);
    float ff = (float)freq;
    float ang = (float)s * ff;               // match fp32 table build in reference
    g_ct[idx] = (float)cos((double)ang);
    g_st[idx] = (float)sin((double)ang);
}

// ---------------- RMSNorm: one block per row (D=768, 256 threads) ----------
__global__ void rmsnorm_kernel(const float* __restrict__ in,
                               const float* __restrict__ w,
                               float* __restrict__ out) {
    int row = blockIdx.x;
    int tid = threadIdx.x;
    const float* p = in + (size_t)row * D_;
    float v0 = p[tid], v1 = p[tid + 256], v2 = p[tid + 512];
    float ss = v0 * v0 + v1 * v1 + v2 * v2;
    __shared__ float red[256];
    red[tid] = ss;
    __syncthreads();
    for (int o = 128; o > 0; o >>= 1) {
        if (tid < o) red[tid] += red[tid + o];
        __syncthreads();
    }
    float inv = rsqrtf(red[0] * (1.0f / (float)D_) + 1e-6f);
    float* q = out + (size_t)row * D_;
    q[tid]       = v0 * inv * w[tid];
    q[tid + 256] = v1 * inv * w[tid + 256];
    q[tid + 512] = v2 * inv * w[tid + 512];
}

// ---------------- RoPE (in place) ------------------------------------------
__global__ void rope_kernel(float* __restrict__ t, int nh, int total) {
    int idx = blockIdx.x * blockDim.x + threadIdx.x;
    if (idx >= total) return;
    int i   = idx % HALF_HD_;
    int hh  = (idx / HALF_HD_) % nh;
    int row = idx / (HALF_HD_ * nh);
    int s   = row % S_;
    float c  = g_ct[s * HALF_HD_ + i];
    float sn = g_st[s * HALF_HD_ + i];
    size_t base = ((size_t)row * nh + hh) * HD_ + 2 * i;
    float t0 = t[base], t1 = t[base + 1];
    t[base]     = t0 * c - t1 * sn;
    t[base + 1] = t0 * sn + t1 * c;
}

// ---------------- Generic tiled SGEMM --------------------------------------
// MODE 0: C = A @ B                      (dense, row-major)
// MODE 1: C = A @ B + R                  (residual add)
// MODE 2: scores = Q @ K^T, batched over z = b*H + h, causal block-skip
// MODE 3: attn   = P @ V,   batched over z, causal K-limit
template<int BM, int BN, int BK, int TM, int TN, int MODE>
__global__ void __launch_bounds__((BM/TM)*(BN/TN))
gemm_k(const float* __restrict__ A, const float* __restrict__ Bm,
       const float* __restrict__ R, float* __restrict__ C,
       int M, int N, int K, int lda, int ldb, int ldc) {
    constexpr int NT = (BM/TM)*(BN/TN);
    const int tid = threadIdx.x;
    const int m0 = blockIdx.y * BM;
    const int n0 = blockIdx.x * BN;

    if (MODE == 2 || MODE == 3) {
        int z = blockIdx.z, b = z / H_, h = z % H_, kvh = h / NREP_;
        if (MODE == 2) {
            if (n0 >= m0 + BM) return;               // fully masked tile
            A  += (size_t)b * S_ * D_ + (size_t)h * HD_;
            Bm += (size_t)b * S_ * (KVH_*HD_) + (size_t)kvh * HD_;
            C  += (size_t)z * S_ * S_;
        } else {
            A  += (size_t)z * S_ * S_;
            Bm += (size_t)b * S_ * (KVH_*HD_) + (size_t)kvh * HD_;
            C  += (size_t)b * S_ * D_ + (size_t)h * HD_;
        }
    }
    int kend = K;
    if (MODE == 3) { int kl = m0 + BM; kend = kl < K ? kl : K; }

    __shared__ __align__(16) float As[BK][BM];
    __shared__ __align__(16) float Bs[BK][BN];

    float acc[TM][TN];
#pragma unroll
    for (int i = 0; i < TM; i++)
#pragma unroll
        for (int j = 0; j < TN; j++) acc[i][j] = 0.0f;

    const int ty = tid / (BN/TN);
    const int tx = tid % (BN/TN);

    for (int k0 = 0; k0 < kend; k0 += BK) {
        // Load A tile (BM x BK), transposed store
#pragma unroll
        for (int t = tid; t < BM*(BK/4); t += NT) {
            int m  = t / (BK/4);
            int kq = (t % (BK/4)) * 4;
            float4 v = *(const float4*)(A + (size_t)(m0 + m) * lda + k0 + kq);
            As[kq + 0][m] = v.x; As[kq + 1][m] = v.y;
            As[kq + 2][m] = v.z; As[kq + 3][m] = v.w;
        }
        // Load B tile
        if (MODE == 2) { // B^T: rows are n, contiguous along k
#pragma unroll
            for (int t = tid; t < BN*(BK/4); t += NT) {
                int n  = t / (BK/4);
                int kq = (t % (BK/4)) * 4;
                float4 v = *(const float4*)(Bm + (size_t)(n0 + n) * ldb + k0 + kq);
                Bs[kq + 0][n] = v.x; Bs[kq + 1][n] = v.y;
                Bs[kq + 2][n] = v.z; Bs[kq + 3][n] = v.w;
            }
        } else {        // row-major B: rows are k, contiguous along n
#pragma unroll
            for (int t = tid; t < BK*(BN/4); t += NT) {
                int kk = t / (BN/4);
                int nq = (t % (BN/4)) * 4;
                *(float4*)&Bs[kk][nq] =
                    *(const float4*)(Bm + (size_t)(k0 + kk) * ldb + n0 + nq);
            }
        }
        __syncthreads();

#pragma unroll
        for (int kk = 0; kk < BK; kk++) {
            float ra[TM], rb[TN];
#pragma unroll
            for (int i = 0; i < TM; i++) ra[i] = As[kk][ty*TM + i];
#pragma unroll
            for (int j = 0; j < TN; j++) rb[j] = Bs[kk][tx*TN + j];
#pragma unroll
            for (int i = 0; i < TM; i++)
#pragma unroll
                for (int j = 0; j < TN; j++) acc[i][j] += ra[i] * rb[j];
        }
        __syncthreads();
    }

#pragma unroll
    for (int i = 0; i < TM; i++) {
        size_t roff = (size_t)(m0 + ty*TM + i) * ldc + n0 + tx*TN;
#pragma unroll
        for (int j = 0; j < TN; j++) {
            float v = acc[i][j];
            if (MODE == 1) v += R[roff + j];
            C[roff + j] = v;
        }
    }
}

// ---------------- Causal softmax over scores (in place -> probs) -----------
__global__ void softmax_kernel() {
    int q = blockIdx.x;
    int z = blockIdx.y;
    int tid = threadIdx.x;
    float* p = g_sc + (size_t)z * S_ * S_ + (size_t)q * S_;
    int n = q + 1;
    const float scale = 0.125f; // 1/sqrt(64)

    __shared__ float red[256];
    float m = -1e30f;
    for (int j = tid; j < n; j += 256) m = fmaxf(m, p[j] * scale);
    red[tid] = m;
    __syncthreads();
    for (int o = 128; o > 0; o >>= 1) {
        if (tid < o) red[tid] = fmaxf(red[tid], red[tid + o]);
        __syncthreads();
    }
    float mx = red[0];
    __syncthreads();

    float sum = 0.0f;
    for (int j = tid; j < n; j += 256) sum += expf(p[j] * scale - mx);
    red[tid] = sum;
    __syncthreads();
    for (int o = 128; o > 0; o >>= 1) {
        if (tid < o) red[tid] += red[tid + o];
        __syncthreads();
    }
    float inv = 1.0f / red[0];

    for (int j = tid; j < n; j += 256) p[j] = expf(p[j] * scale - mx) * inv;
    for (int j = n + tid; j < S_; j += 256) p[j] = 0.0f;
}

// ---------------- SwiGLU: f0 = silu(f0) * f1 -------------------------------
__global__ void silu_mul_kernel() {
    int idx = blockIdx.x * blockDim.x + threadIdx.x;
    if (idx >= T_ * FF_) return;
    float a = g_f0[idx];
    float b = g_f1[idx];
    g_f0[idx] = a / (1.0f + expf(-a)) * b;
}

// ---------------- Launch ----------------------------------------------------
extern "C" void kernel_launch(void* const* d_in, const int* in_sizes, int n_in,
                              void* d_out, int out_size) {
    const float* x  = (const float*)d_in[0];
    const float* Wq = (const float*)d_in[1];
    const float* Wk = (const float*)d_in[2];
    const float* Wv = (const float*)d_in[3];
    const float* Wo = (const float*)d_in[4];
    const float* an = (const float*)d_in[5];
    const float* w0 = (const float*)d_in[6];
    const float* w1 = (const float*)d_in[7];
    const float* w2 = (const float*)d_in[8];
    const float* sn = (const float*)d_in[9];
    const float* on = (const float*)d_in[10];
    float* out = (float*)d_out;

    float *px, *ph, *pq, *pk, *pvv, *pattn, *pf0, *pf1, *psc;
    cudaGetSymbolAddress((void**)&px,    g_x);
    cudaGetSymbolAddress((void**)&ph,    g_h);
    cudaGetSymbolAddress((void**)&pq,    g_q);
    cudaGetSymbolAddress((void**)&pk,    g_kbuf);
    cudaGetSymbolAddress((void**)&pvv,   g_vbuf);
    cudaGetSymbolAddress((void**)&pattn, g_attn);
    cudaGetSymbolAddress((void**)&pf0,   g_f0);
    cudaGetSymbolAddress((void**)&pf1,   g_f1);
    cudaGetSymbolAddress((void**)&psc,   g_sc);

    rope_table_kernel<<<(S_*HALF_HD_ + 255)/256, 256>>>();

    for (int i = 0; i < L_; i++) {
        const float* xin = (i == 0) ? x : px;

        // attn-norm
        rmsnorm_kernel<<<T_, 256>>>(xin, an + (size_t)i * D_, ph);

        // QKV projections (256-thread blocks: (128/8)*(128/8))
        gemm_k<128,128,16,8,8,0><<<dim3(D_/128, T_/128), 256>>>(
            ph, Wq + (size_t)i*D_*D_, nullptr, pq, T_, D_, D_, D_, D_, D_);
        gemm_k<128,128,16,8,8,0><<<dim3((KVH_*HD_)/128, T_/128), 256>>>(
            ph, Wk + (size_t)i*D_*(KVH_*HD_), nullptr, pk,
            T_, KVH_*HD_, D_, D_, KVH_*HD_, KVH_*HD_);
        gemm_k<128,128,16,8,8,0><<<dim3((KVH_*HD_)/128, T_/128), 256>>>(
            ph, Wv + (size_t)i*D_*(KVH_*HD_), nullptr, pvv,
            T_, KVH_*HD_, D_, D_, KVH_*HD_, KVH_*HD_);

        // RoPE on q, k
        {
            int tq = T_ * H_ * HALF_HD_;
            rope_kernel<<<(tq + 255)/256, 256>>>(pq, H_, tq);
            int tk = T_ * KVH_ * HALF_HD_;
            rope_kernel<<<(tk + 255)/256, 256>>>(pk, KVH_, tk);
        }

        // scores = Q K^T (batched over 24 (b,h) pairs, causal skip)
        gemm_k<128,128,16,8,8,2><<<dim3(S_/128, S_/128, B_*H_), 256>>>(
            pq, pk, nullptr, psc, S_, S_, HD_, D_, KVH_*HD_, S_);

        // causal softmax
        softmax_kernel<<<dim3(S_, B_*H_), 256>>>();

        // attn = P V (causal K-limit; 128-thread blocks: (64/4)*(64/8))
        gemm_k<64,64,16,4,8,3><<<dim3(1, S_/64, B_*H_), 128>>>(
            psc, pvv, nullptr, pattn, S_, HD_, S_, S_, KVH_*HD_, D_);

        // h2 = x + attn @ Wo
        gemm_k<128,128,16,8,8,1><<<dim3(D_/128, T_/128), 256>>>(
            pattn, Wo + (size_t)i*D_*D_, xin, px, T_, D_, D_, D_, D_, D_);

        // ffn-norm
        rmsnorm_kernel<<<T_, 256>>>(px, sn + (size_t)i * D_, ph);

        // FFN
        gemm_k<128,128,16,8,8,0><<<dim3(FF_/128, T_/128), 256>>>(
            ph, w0 + (size_t)i*D_*FF_, nullptr, pf0, T_, FF_, D_, D_, FF_, FF_);
        gemm_k<128,128,16,8,8,0><<<dim3(FF_/128, T_/128), 256>>>(
            ph, w1 + (size_t)i*D_*FF_, nullptr, pf1, T_, FF_, D_, D_, FF_, FF_);
        silu_mul_kernel<<<(T_*FF_ + 255)/256, 256>>>();
        gemm_k<128,128,16,8,8,1><<<dim3(D_/128, T_/128), 256>>>(
            pf0, w2 + (size_t)i*FF_*D_, px, px, T_, D_, FF_, FF_, D_, D_);
    }

    // final norm
    rmsnorm_kernel<<<T_, 256>>>(px, on, out);
}

// round 7
// speedup vs baseline: 1.3689x; 1.3689x over previous
#include <cuda_runtime.h>
#include <math.h>
#include <stdint.h>

// Problem constants
#define L_    2
#define B_    2
#define S_    2048
#define D_    768
#define H_    12
#define KVH_  4
#define HD_   64
#define NREP_ 3
#define FF_   3072
#define T_    (B_*S_)          // 4096 tokens
#define HALF_HD_ 32

// ---------------- Scratch (device globals; no allocation allowed) ----------
__device__ float g_x[T_*D_];          // running residual stream
__device__ float g_h[T_*D_];          // normed activations
__device__ float g_q[T_*D_];          // Q  [T, H, HD]
__device__ float g_kbuf[T_*KVH_*HD_]; // K  [T, KVH, HD]
__device__ float g_vbuf[T_*KVH_*HD_]; // V  [T, KVH, HD]
__device__ float g_attn[T_*D_];       // attention output [T, H, HD]
__device__ float g_f0[T_*FF_];        // FFN gate / fused
__device__ float g_f1[T_*FF_];        // FFN up
__device__ float g_sc[(size_t)B_*H_*S_*S_]; // scores/probs (402 MB)
__device__ float g_ct[S_*HALF_HD_];   // rope cos table
__device__ float g_st[S_*HALF_HD_];   // rope sin table

// ---------------- RoPE tables ----------------------------------------------
__global__ void rope_table_kernel() {
    int idx = blockIdx.x * blockDim.x + threadIdx.x;
    if (idx >= S_ * HALF_HD_) return;
    int s = idx / HALF_HD_;
    int i = idx % HALF_HD_;
    double freq = exp(-log(10000.0) * (double)(2 * i) / (double)HD_);
    float ff = (float)freq;
    float ang = (float)s * ff;
    g_ct[idx] = (float)cos((double)ang);
    g_st[idx] = (float)sin((double)ang);
}

// ---------------- RMSNorm ---------------------------------------------------
__global__ void rmsnorm_kernel(const float* __restrict__ in,
                               const float* __restrict__ w,
                               float* __restrict__ out) {
    int row = blockIdx.x;
    int tid = threadIdx.x;
    const float* p = in + (size_t)row * D_;
    float v0 = p[tid], v1 = p[tid + 256], v2 = p[tid + 512];
    float ss = v0 * v0 + v1 * v1 + v2 * v2;
    __shared__ float red[256];
    red[tid] = ss;
    __syncthreads();
    for (int o = 128; o > 0; o >>= 1) {
        if (tid < o) red[tid] += red[tid + o];
        __syncthreads();
    }
    float inv = rsqrtf(red[0] * (1.0f / (float)D_) + 1e-6f);
    float* q = out + (size_t)row * D_;
    q[tid]       = v0 * inv * w[tid];
    q[tid + 256] = v1 * inv * w[tid + 256];
    q[tid + 512] = v2 * inv * w[tid + 512];
}

// ---------------- RoPE (in place) -------------------------------------------
__global__ void rope_kernel(float* __restrict__ t, int nh, int total) {
    int idx = blockIdx.x * blockDim.x + threadIdx.x;
    if (idx >= total) return;
    int i   = idx % HALF_HD_;
    int hh  = (idx / HALF_HD_) % nh;
    int row = idx / (HALF_HD_ * nh);
    int s   = row % S_;
    float c  = g_ct[s * HALF_HD_ + i];
    float sn = g_st[s * HALF_HD_ + i];
    size_t base = ((size_t)row * nh + hh) * HD_ + 2 * i;
    float t0 = t[base], t1 = t[base + 1];
    t[base]     = t0 * c - t1 * sn;
    t[base + 1] = t0 * sn + t1 * c;
}

// ---------------- tf32 helpers ----------------------------------------------
__device__ __forceinline__ void split_tf32(float x, uint32_t& hi, uint32_t& lo) {
    uint32_t h;
    asm("cvt.rna.tf32.f32 %0, %1;" : "=r"(h) : "f"(x));
    float hf = __uint_as_float(h);
    float l = x - hf;
    uint32_t lw;
    asm("cvt.rna.tf32.f32 %0, %1;" : "=r"(lw) : "f"(l));
    hi = h; lo = lw;
}

__device__ __forceinline__ void mma_tf32(float* c, const uint32_t* a, const uint32_t* b) {
    asm volatile(
        "mma.sync.aligned.m16n8k8.row.col.f32.tf32.tf32.f32 "
        "{%0,%1,%2,%3}, {%4,%5,%6,%7}, {%8,%9}, {%0,%1,%2,%3};"
        : "+f"(c[0]), "+f"(c[1]), "+f"(c[2]), "+f"(c[3])
        : "r"(a[0]), "r"(a[1]), "r"(a[2]), "r"(a[3]), "r"(b[0]), "r"(b[1]));
}

// ---------------- Tensor-core GEMM (tf32 x3 split, fp32-accurate) -----------
// MODE 0: C = A @ B                      (dense, row-major)
// MODE 1: C = A @ B + R                  (residual add)
// MODE 2: scores = Q @ K^T, batched over z = b*H + h, causal block-skip
// MODE 3: attn   = P @ V,   batched over z, causal K-limit
// A is always row-major with contiguous k. B global layout:
//   MODE 0/1/3: row-major [k][n]  -> smem k-major
//   MODE 2:     K matrix  [n][k]  -> smem n-major
template<int BM, int BN, int BK, int WM, int WN, int MODE>
__global__ void __launch_bounds__(256, 1)
mma_gemm(const float* __restrict__ A, const float* __restrict__ Bm,
         const float* __restrict__ R, float* __restrict__ C,
         int K, int lda, int ldb, int ldc)
{
    const int m0 = blockIdx.y * BM;
    const int n0 = blockIdx.x * BN;

    if (MODE == 2 || MODE == 3) {
        int z = blockIdx.z, b = z / H_, h = z % H_, kvh = h / NREP_;
        if (MODE == 2) {
            if (n0 >= m0 + BM) return;               // fully masked tile
            A  += (size_t)b * S_ * D_ + (size_t)h * HD_;
            Bm += (size_t)b * S_ * (KVH_*HD_) + (size_t)kvh * HD_;
            C  += (size_t)z * S_ * S_;
        } else {
            A  += (size_t)z * S_ * S_;
            Bm += (size_t)b * S_ * (KVH_*HD_) + (size_t)kvh * HD_;
            C  += (size_t)b * S_ * D_ + (size_t)h * HD_;
        }
    }
    int kend = K;
    if (MODE == 3) { int kl = m0 + BM; kend = kl < K ? kl : K; }
    const int nk = kend / BK;

    constexpr int PAD = 4;
    constexpr int BR = (MODE == 2) ? BN : BK;    // smem B rows
    constexpr int BC = (MODE == 2) ? BK : BN;    // smem B cols
    __shared__ __align__(16) float As[2][BM][BK + PAD];
    __shared__ __align__(16) float Bs[2][BR][BC + PAD];

    const int tid  = threadIdx.x;
    const int lane = tid & 31;
    const int warp = tid >> 5;
    constexpr int NWM = BM / WM;
    const int wm = warp % NWM;
    const int wn = warp / NWM;
    constexpr int MT  = WM / 16;
    constexpr int NT2 = WN / 8;

    const int qr = lane >> 2;   // 0..7
    const int qc = lane & 3;    // 0..3

    float acc[MT][NT2][4];
#pragma unroll
    for (int mt = 0; mt < MT; mt++)
#pragma unroll
        for (int nt = 0; nt < NT2; nt++)
#pragma unroll
            for (int r = 0; r < 4; r++) acc[mt][nt][r] = 0.0f;

    constexpr int NTH = 256;
    constexpr int ACH = BM * BK / 4;   // 16B chunks in A tile
    constexpr int BCH = BR * BC / 4;

    auto loadA = [&](int kt, int s) {
#pragma unroll
        for (int i = 0; i < ACH / NTH; i++) {
            int ch  = tid + i * NTH;
            int row = ch / (BK / 4);
            int kq  = (ch % (BK / 4)) * 4;
            const float* src = A + (size_t)(m0 + row) * lda + kt * BK + kq;
            uint32_t dst = (uint32_t)__cvta_generic_to_shared(&As[s][row][kq]);
            asm volatile("cp.async.cg.shared.global [%0], [%1], 16;" :: "r"(dst), "l"(src));
        }
    };
    auto loadB = [&](int kt, int s) {
#pragma unroll
        for (int i = 0; i < BCH / NTH; i++) {
            int ch  = tid + i * NTH;
            int row = ch / (BC / 4);
            int cq  = (ch % (BC / 4)) * 4;
            const float* src;
            if (MODE == 2) src = Bm + (size_t)(n0 + row) * ldb + kt * BK + cq; // row=n
            else           src = Bm + (size_t)(kt * BK + row) * ldb + n0 + cq; // row=k
            uint32_t dst = (uint32_t)__cvta_generic_to_shared(&Bs[s][row][cq]);
            asm volatile("cp.async.cg.shared.global [%0], [%1], 16;" :: "r"(dst), "l"(src));
        }
    };

    loadA(0, 0); loadB(0, 0);
    asm volatile("cp.async.commit_group;");

    for (int kt = 0; kt < nk; kt++) {
        const int s = kt & 1;
        if (kt + 1 < nk) {
            loadA(kt + 1, s ^ 1); loadB(kt + 1, s ^ 1);
            asm volatile("cp.async.commit_group;");
            asm volatile("cp.async.wait_group 1;");
        } else {
            asm volatile("cp.async.wait_group 0;");
        }
        __syncthreads();

#pragma unroll
        for (int ks = 0; ks < BK; ks += 8) {
            uint32_t ahi[MT][4], alo[MT][4];
#pragma unroll
            for (int mt = 0; mt < MT; mt++) {
                int m = wm * WM + mt * 16 + qr;
                float a0 = As[s][m    ][ks + qc];
                float a1 = As[s][m + 8][ks + qc];
                float a2 = As[s][m    ][ks + qc + 4];
                float a3 = As[s][m + 8][ks + qc + 4];
                split_tf32(a0, ahi[mt][0], alo[mt][0]);
                split_tf32(a1, ahi[mt][1], alo[mt][1]);
                split_tf32(a2, ahi[mt][2], alo[mt][2]);
                split_tf32(a3, ahi[mt][3], alo[mt][3]);
            }
            uint32_t bhi[NT2][2], blo[NT2][2];
#pragma unroll
            for (int nt = 0; nt < NT2; nt++) {
                int n = wn * WN + nt * 8 + qr;
                float b0, b1;
                if (MODE == 2) { b0 = Bs[s][n][ks + qc]; b1 = Bs[s][n][ks + qc + 4]; }
                else           { b0 = Bs[s][ks + qc][n]; b1 = Bs[s][ks + qc + 4][n]; }
                split_tf32(b0, bhi[nt][0], blo[nt][0]);
                split_tf32(b1, bhi[nt][1], blo[nt][1]);
            }
#pragma unroll
            for (int mt = 0; mt < MT; mt++)
#pragma unroll
                for (int nt = 0; nt < NT2; nt++) {
                    mma_tf32(acc[mt][nt], ahi[mt], blo[nt]);
                    mma_tf32(acc[mt][nt], alo[mt], bhi[nt]);
                    mma_tf32(acc[mt][nt], ahi[mt], bhi[nt]);
                }
        }
        __syncthreads();
    }

    // Epilogue
#pragma unroll
    for (int mt = 0; mt < MT; mt++)
#pragma unroll
        for (int nt = 0; nt < NT2; nt++) {
            int m = m0 + wm * WM + mt * 16 + qr;
            int n = n0 + wn * WN + nt * 8 + 2 * qc;
            size_t o0 = (size_t)m * ldc + n;
            size_t o1 = (size_t)(m + 8) * ldc + n;
            float2 v0 = make_float2(acc[mt][nt][0], acc[mt][nt][1]);
            float2 v1 = make_float2(acc[mt][nt][2], acc[mt][nt][3]);
            if (MODE == 1) {
                v0.x += R[o0]; v0.y += R[o0 + 1];
                v1.x += R[o1]; v1.y += R[o1 + 1];
            }
            *(float2*)(C + o0) = v0;
            *(float2*)(C + o1) = v1;
        }
}

// ---------------- Causal softmax over scores (in place -> probs) -----------
__global__ void softmax_kernel() {
    int q = blockIdx.x;
    int z = blockIdx.y;
    int tid = threadIdx.x;
    float* p = g_sc + (size_t)z * S_ * S_ + (size_t)q * S_;
    int n = q + 1;
    const float scale = 0.125f; // 1/sqrt(64)

    __shared__ float red[256];
    float m = -1e30f;
    for (int j = tid; j < n; j += 256) m = fmaxf(m, p[j] * scale);
    red[tid] = m;
    __syncthreads();
    for (int o = 128; o > 0; o >>= 1) {
        if (tid < o) red[tid] = fmaxf(red[tid], red[tid + o]);
        __syncthreads();
    }
    float mx = red[0];
    __syncthreads();

    float sum = 0.0f;
    for (int j = tid; j < n; j += 256) sum += expf(p[j] * scale - mx);
    red[tid] = sum;
    __syncthreads();
    for (int o = 128; o > 0; o >>= 1) {
        if (tid < o) red[tid] += red[tid + o];
        __syncthreads();
    }
    float inv = 1.0f / red[0];

    for (int j = tid; j < n; j += 256) p[j] = expf(p[j] * scale - mx) * inv;
    for (int j = n + tid; j < S_; j += 256) p[j] = 0.0f;
}

// ---------------- SwiGLU: f0 = silu(f0) * f1 -------------------------------
__global__ void silu_mul_kernel() {
    int idx = blockIdx.x * blockDim.x + threadIdx.x;
    if (idx >= T_ * FF_) return;
    float a = g_f0[idx];
    float b = g_f1[idx];
    g_f0[idx] = a / (1.0f + expf(-a)) * b;
}

// ---------------- Launch ----------------------------------------------------
extern "C" void kernel_launch(void* const* d_in, const int* in_sizes, int n_in,
                              void* d_out, int out_size) {
    const float* x  = (const float*)d_in[0];
    const float* Wq = (const float*)d_in[1];
    const float* Wk = (const float*)d_in[2];
    const float* Wv = (const float*)d_in[3];
    const float* Wo = (const float*)d_in[4];
    const float* an = (const float*)d_in[5];
    const float* w0 = (const float*)d_in[6];
    const float* w1 = (const float*)d_in[7];
    const float* w2 = (const float*)d_in[8];
    const float* sn = (const float*)d_in[9];
    const float* on = (const float*)d_in[10];
    float* out = (float*)d_out;

    float *px, *ph, *pq, *pk, *pvv, *pattn, *pf0, *pf1, *psc;
    cudaGetSymbolAddress((void**)&px,    g_x);
    cudaGetSymbolAddress((void**)&ph,    g_h);
    cudaGetSymbolAddress((void**)&pq,    g_q);
    cudaGetSymbolAddress((void**)&pk,    g_kbuf);
    cudaGetSymbolAddress((void**)&pvv,   g_vbuf);
    cudaGetSymbolAddress((void**)&pattn, g_attn);
    cudaGetSymbolAddress((void**)&pf0,   g_f0);
    cudaGetSymbolAddress((void**)&pf1,   g_f1);
    cudaGetSymbolAddress((void**)&psc,   g_sc);

    rope_table_kernel<<<(S_*HALF_HD_ + 255)/256, 256>>>();

    for (int i = 0; i < L_; i++) {
        const float* xin = (i == 0) ? x : px;

        // attn-norm
        rmsnorm_kernel<<<T_, 256>>>(xin, an + (size_t)i * D_, ph);

        // QKV projections
        mma_gemm<128,128,16,32,64,0><<<dim3(D_/128, T_/128), 256>>>(
            ph, Wq + (size_t)i*D_*D_, nullptr, pq, D_, D_, D_, D_);
        mma_gemm<128,128,16,32,64,0><<<dim3((KVH_*HD_)/128, T_/128), 256>>>(
            ph, Wk + (size_t)i*D_*(KVH_*HD_), nullptr, pk,
            D_, D_, KVH_*HD_, KVH_*HD_);
        mma_gemm<128,128,16,32,64,0><<<dim3((KVH_*HD_)/128, T_/128), 256>>>(
            ph, Wv + (size_t)i*D_*(KVH_*HD_), nullptr, pvv,
            D_, D_, KVH_*HD_, KVH_*HD_);

        // RoPE on q, k
        {
            int tq = T_ * H_ * HALF_HD_;
            rope_kernel<<<(tq + 255)/256, 256>>>(pq, H_, tq);
            int tk = T_ * KVH_ * HALF_HD_;
            rope_kernel<<<(tk + 255)/256, 256>>>(pk, KVH_, tk);
        }

        // scores = Q K^T (batched over 24 (b,h), causal block-skip)
        mma_gemm<128,128,16,32,64,2><<<dim3(S_/128, S_/128, B_*H_), 256>>>(
            pq, pk, nullptr, psc, HD_, D_, KVH_*HD_, S_);

        // causal softmax
        softmax_kernel<<<dim3(S_, B_*H_), 256>>>();

        // attn = P V (causal K-limit)
        mma_gemm<128,64,16,32,32,3><<<dim3(1, S_/128, B_*H_), 256>>>(
            psc, pvv, nullptr, pattn, S_, S_, KVH_*HD_, D_);

        // h2 = x + attn @ Wo
        mma_gemm<128,128,16,32,64,1><<<dim3(D_/128, T_/128), 256>>>(
            pattn, Wo + (size_t)i*D_*D_, xin, px, D_, D_, D_, D_);

        // ffn-norm
        rmsnorm_kernel<<<T_, 256>>>(px, sn + (size_t)i * D_, ph);

        // FFN
        mma_gemm<128,128,16,32,64,0><<<dim3(FF_/128, T_/128), 256>>>(
            ph, w0 + (size_t)i*D_*FF_, nullptr, pf0, D_, D_, FF_, FF_);
        mma_gemm<128,128,16,32,64,0><<<dim3(FF_/128, T_/128), 256>>>(
            ph, w1 + (size_t)i*D_*FF_, nullptr, pf1, D_, D_, FF_, FF_);
        silu_mul_kernel<<<(T_*FF_ + 255)/256, 256>>>();
        mma_gemm<128,128,16,32,64,1><<<dim3(D_/128, T_/128), 256>>>(
            pf0, w2 + (size_t)i*FF_*D_, px, px, FF_, FF_, D_, D_);
    }

    // final norm
    rmsnorm_kernel<<<T_, 256>>>(px, on, out);
}

// round 10
// speedup vs baseline: 1.4572x; 1.0646x over previous
#include <cuda_runtime.h>
#include <math.h>
#include <stdint.h>

// Problem constants
#define L_    2
#define B_    2
#define S_    2048
#define D_    768
#define H_    12
#define KVH_  4
#define HD_   64
#define NREP_ 3
#define FF_   3072
#define T_    (B_*S_)          // 4096 tokens
#define HALF_HD_ 32

// Flash tile config
#define BMF 64
#define BNF 64
#define FPAD 4
#define FSTR (BNF + FPAD)                 // 68 floats per row
#define FSMEM_BYTES (3 * 64 * FSTR * 4)   // K + V + QP tiles = 52224 B

// ---------------- Scratch (device globals; no allocation allowed) ----------
__device__ float g_x[T_*D_];          // running residual stream
__device__ float g_h[T_*D_];          // normed activations
__device__ float g_q[T_*D_];          // Q  [T, H, HD]
__device__ float g_kbuf[T_*KVH_*HD_]; // K  [T, KVH, HD]
__device__ float g_vbuf[T_*KVH_*HD_]; // V  [T, KVH, HD]
__device__ float g_attn[T_*D_];       // attention output [T, H, HD]
__device__ float g_f0[T_*FF_];        // FFN gate / fused
__device__ float g_f1[T_*FF_];        // FFN up
__device__ float g_ct[S_*HALF_HD_];   // rope cos table
__device__ float g_st[S_*HALF_HD_];   // rope sin table

// ---------------- RoPE tables ----------------------------------------------
__global__ void rope_table_kernel() {
    int idx = blockIdx.x * blockDim.x + threadIdx.x;
    if (idx >= S_ * HALF_HD_) return;
    int s = idx / HALF_HD_;
    int i = idx % HALF_HD_;
    double freq = exp(-log(10000.0) * (double)(2 * i) / (double)HD_);
    float ff = (float)freq;
    float ang = (float)s * ff;
    g_ct[idx] = (float)cos((double)ang);
    g_st[idx] = (float)sin((double)ang);
}

// ---------------- RMSNorm ---------------------------------------------------
__global__ void rmsnorm_kernel(const float* __restrict__ in,
                               const float* __restrict__ w,
                               float* __restrict__ out) {
    int row = blockIdx.x;
    int tid = threadIdx.x;
    const float* p = in + (size_t)row * D_;
    float v0 = p[tid], v1 = p[tid + 256], v2 = p[tid + 512];
    float ss = v0 * v0 + v1 * v1 + v2 * v2;
    __shared__ float red[256];
    red[tid] = ss;
    __syncthreads();
    for (int o = 128; o > 0; o >>= 1) {
        if (tid < o) red[tid] += red[tid + o];
        __syncthreads();
    }
    float inv = rsqrtf(red[0] * (1.0f / (float)D_) + 1e-6f);
    float* q = out + (size_t)row * D_;
    q[tid]       = v0 * inv * w[tid];
    q[tid + 256] = v1 * inv * w[tid + 256];
    q[tid + 512] = v2 * inv * w[tid + 512];
}

// ---------------- RoPE (in place) -------------------------------------------
__global__ void rope_kernel(float* __restrict__ t, int nh, int total) {
    int idx = blockIdx.x * blockDim.x + threadIdx.x;
    if (idx >= total) return;
    int i   = idx % HALF_HD_;
    int hh  = (idx / HALF_HD_) % nh;
    int row = idx / (HALF_HD_ * nh);
    int s   = row % S_;
    float c  = g_ct[s * HALF_HD_ + i];
    float sn = g_st[s * HALF_HD_ + i];
    size_t base = ((size_t)row * nh + hh) * HD_ + 2 * i;
    float t0 = t[base], t1 = t[base + 1];
    t[base]     = t0 * c - t1 * sn;
    t[base + 1] = t0 * sn + t1 * c;
}

// ---------------- tf32 helpers ----------------------------------------------
__device__ __forceinline__ void split_tf32(float x, uint32_t& hi, uint32_t& lo) {
    uint32_t h;
    asm("cvt.rna.tf32.f32 %0, %1;" : "=r"(h) : "f"(x));
    float hf = __uint_as_float(h);
    float l = x - hf;
    uint32_t lw;
    asm("cvt.rna.tf32.f32 %0, %1;" : "=r"(lw) : "f"(l));
    hi = h; lo = lw;
}

__device__ __forceinline__ void mma_tf32(float* c, const uint32_t* a, const uint32_t* b) {
    asm volatile(
        "mma.sync.aligned.m16n8k8.row.col.f32.tf32.tf32.f32 "
        "{%0,%1,%2,%3}, {%4,%5,%6,%7}, {%8,%9}, {%0,%1,%2,%3};"
        : "+f"(c[0]), "+f"(c[1]), "+f"(c[2]), "+f"(c[3])
        : "r"(a[0]), "r"(a[1]), "r"(a[2]), "r"(a[3]), "r"(b[0]), "r"(b[1]));
}

// ---------------- Tensor-core GEMM (tf32 x3 split, fp32-accurate) -----------
// MODE 0: C = A @ B      MODE 1: C = A @ B + R
template<int BM, int BN, int BK, int WM, int WN, int MODE>
__global__ void __launch_bounds__(256, 2)
mma_gemm(const float* __restrict__ A, const float* __restrict__ Bm,
         const float* __restrict__ R, float* __restrict__ C,
         int K, int lda, int ldb, int ldc)
{
    const int m0 = blockIdx.y * BM;
    const int n0 = blockIdx.x * BN;
    const int nk = K / BK;

    constexpr int PAD = 4;
    __shared__ __align__(16) float As[2][BM][BK + PAD];
    __shared__ __align__(16) float Bs[2][BK][BN + PAD];

    const int tid  = threadIdx.x;
    const int lane = tid & 31;
    const int warp = tid >> 5;
    constexpr int NWM = BM / WM;
    const int wm = warp % NWM;
    const int wn = warp / NWM;
    constexpr int MT  = WM / 16;
    constexpr int NT2 = WN / 8;

    const int qr = lane >> 2;
    const int qc = lane & 3;

    float acc[MT][NT2][4];
#pragma unroll
    for (int mt = 0; mt < MT; mt++)
#pragma unroll
        for (int nt = 0; nt < NT2; nt++)
#pragma unroll
            for (int r = 0; r < 4; r++) acc[mt][nt][r] = 0.0f;

    constexpr int NTH = 256;
    constexpr int ACH = BM * BK / 4;
    constexpr int BCH = BK * BN / 4;

    auto loadA = [&](int kt, int s) {
#pragma unroll
        for (int i = 0; i < ACH / NTH; i++) {
            int ch  = tid + i * NTH;
            int row = ch / (BK / 4);
            int kq  = (ch % (BK / 4)) * 4;
            const float* src = A + (size_t)(m0 + row) * lda + kt * BK + kq;
            uint32_t dst = (uint32_t)__cvta_generic_to_shared(&As[s][row][kq]);
            asm volatile("cp.async.cg.shared.global [%0], [%1], 16;" :: "r"(dst), "l"(src));
        }
    };
    auto loadB = [&](int kt, int s) {
#pragma unroll
        for (int i = 0; i < BCH / NTH; i++) {
            int ch  = tid + i * NTH;
            int row = ch / (BN / 4);
            int cq  = (ch % (BN / 4)) * 4;
            const float* src = Bm + (size_t)(kt * BK + row) * ldb + n0 + cq;
            uint32_t dst = (uint32_t)__cvta_generic_to_shared(&Bs[s][row][cq]);
            asm volatile("cp.async.cg.shared.global [%0], [%1], 16;" :: "r"(dst), "l"(src));
        }
    };

    loadA(0, 0); loadB(0, 0);
    asm volatile("cp.async.commit_group;");

    for (int kt = 0; kt < nk; kt++) {
        const int s = kt & 1;
        if (kt + 1 < nk) {
            loadA(kt + 1, s ^ 1); loadB(kt + 1, s ^ 1);
            asm volatile("cp.async.commit_group;");
            asm volatile("cp.async.wait_group 1;");
        } else {
            asm volatile("cp.async.wait_group 0;");
        }
        __syncthreads();

#pragma unroll
        for (int ks = 0; ks < BK; ks += 8) {
            uint32_t ahi[MT][4], alo[MT][4];
#pragma unroll
            for (int mt = 0; mt < MT; mt++) {
                int m = wm * WM + mt * 16 + qr;
                float a0 = As[s][m    ][ks + qc];
                float a1 = As[s][m + 8][ks + qc];
                float a2 = As[s][m    ][ks + qc + 4];
                float a3 = As[s][m + 8][ks + qc + 4];
                split_tf32(a0, ahi[mt][0], alo[mt][0]);
                split_tf32(a1, ahi[mt][1], alo[mt][1]);
                split_tf32(a2, ahi[mt][2], alo[mt][2]);
                split_tf32(a3, ahi[mt][3], alo[mt][3]);
            }
            uint32_t bhi[NT2][2], blo[NT2][2];
#pragma unroll
            for (int nt = 0; nt < NT2; nt++) {
                int n = wn * WN + nt * 8 + qr;
                float b0 = Bs[s][ks + qc][n];
                float b1 = Bs[s][ks + qc + 4][n];
                split_tf32(b0, bhi[nt][0], blo[nt][0]);
                split_tf32(b1, bhi[nt][1], blo[nt][1]);
            }
#pragma unroll
            for (int mt = 0; mt < MT; mt++)
#pragma unroll
                for (int nt = 0; nt < NT2; nt++) {
                    mma_tf32(acc[mt][nt], ahi[mt], blo[nt]);
                    mma_tf32(acc[mt][nt], alo[mt], bhi[nt]);
                    mma_tf32(acc[mt][nt], ahi[mt], bhi[nt]);
                }
        }
        __syncthreads();
    }

#pragma unroll
    for (int mt = 0; mt < MT; mt++)
#pragma unroll
        for (int nt = 0; nt < NT2; nt++) {
            int m = m0 + wm * WM + mt * 16 + qr;
            int n = n0 + wn * WN + nt * 8 + 2 * qc;
            size_t o0 = (size_t)m * ldc + n;
            size_t o1 = (size_t)(m + 8) * ldc + n;
            float2 v0 = make_float2(acc[mt][nt][0], acc[mt][nt][1]);
            float2 v1 = make_float2(acc[mt][nt][2], acc[mt][nt][3]);
            if (MODE == 1) {
                v0.x += R[o0]; v0.y += R[o0 + 1];
                v1.x += R[o1]; v1.y += R[o1 + 1];
            }
            *(float2*)(C + o0) = v0;
            *(float2*)(C + o1) = v1;
        }
}

// ---------------- Fused flash attention (tf32x3, online softmax) ------------
// One CTA = 64 Q rows of one (b,h). 128 threads, 4 warps * 16 rows.
// smem: Ks[64][68], Vs[64][68], QP[64][68] (Q staging, then P exchange).
__global__ void __launch_bounds__(128)
flash_kernel(const float* __restrict__ Qm, const float* __restrict__ Km,
             const float* __restrict__ Vm, float* __restrict__ Om) {
    extern __shared__ __align__(16) float fsm[];
    float* Ks = fsm;
    float* Vs = fsm + 64 * FSTR;
    float* QP = fsm + 2 * 64 * FSTR;

    const int z = blockIdx.y;
    const int b = z / H_, h = z % H_, kvh = h / NREP_;
    const int q0 = ((int)gridDim.x - 1 - (int)blockIdx.x) * BMF;  // heavy tiles first

    const int tid  = threadIdx.x;
    const int lane = tid & 31;
    const int warp = tid >> 5;
    const int qr = lane >> 2, qc = lane & 3;
    const int wrow = warp * 16;

    const float* Qb = Qm + ((size_t)(b * S_ + q0)) * D_ + h * HD_;
    const float* Kb = Km + ((size_t)b * S_) * (KVH_ * HD_) + kvh * HD_;
    const float* Vb = Vm + ((size_t)b * S_) * (KVH_ * HD_) + kvh * HD_;

    // stage Q tile
    for (int i = tid; i < 64 * 16; i += 128) {
        int r = i >> 4, cq = (i & 15) << 2;
        *(float4*)&QP[r * FSTR + cq] = *(const float4*)(Qb + (size_t)r * D_ + cq);
    }
    __syncthreads();

    // Q fragments (scaled by 1/sqrt(HD)), split hi/lo
    uint32_t qhi[8][4], qlo[8][4];
#pragma unroll
    for (int ks = 0; ks < 8; ks++) {
        float a0 = QP[(wrow + qr    ) * FSTR + ks * 8 + qc    ] * 0.125f;
        float a1 = QP[(wrow + qr + 8) * FSTR + ks * 8 + qc    ] * 0.125f;
        float a2 = QP[(wrow + qr    ) * FSTR + ks * 8 + qc + 4] * 0.125f;
        float a3 = QP[(wrow + qr + 8) * FSTR + ks * 8 + qc + 4] * 0.125f;
        split_tf32(a0, qhi[ks][0], qlo[ks][0]);
        split_tf32(a1, qhi[ks][1], qlo[ks][1]);
        split_tf32(a2, qhi[ks][2], qlo[ks][2]);
        split_tf32(a3, qhi[ks][3], qlo[ks][3]);
    }

    float m0 = -INFINITY, m1 = -INFINITY, l0 = 0.f, l1 = 0.f;
    float oa[8][4];
#pragma unroll
    for (int nt = 0; nt < 8; nt++)
#pragma unroll
        for (int r = 0; r < 4; r++) oa[nt][r] = 0.f;

    const int niter = q0 / BNF + 1;
    for (int it = 0; it < niter; it++) {
        const int j0 = it * BNF;
        const bool diag = (j0 == q0);

        __syncthreads();   // prior iteration's consumers done with Ks/Vs/QP
        for (int i = tid; i < 64 * 16; i += 128) {
            int r = i >> 4, cq = (i & 15) << 2;
            *(float4*)&Ks[r * FSTR + cq] =
                *(const float4*)(Kb + (size_t)(j0 + r) * (KVH_ * HD_) + cq);
            *(float4*)&Vs[r * FSTR + cq] =
                *(const float4*)(Vb + (size_t)(j0 + r) * (KVH_ * HD_) + cq);
        }
        __syncthreads();

        // S = Q @ K^T  (16 x 64 per warp)
        float sa[8][4];
#pragma unroll
        for (int nt = 0; nt < 8; nt++)
#pragma unroll
            for (int r = 0; r < 4; r++) sa[nt][r] = 0.f;

#pragma unroll
        for (int ks = 0; ks < 8; ks++) {
            uint32_t bhi[8][2], blo[8][2];
#pragma unroll
            for (int nt = 0; nt < 8; nt++) {
                float b0 = Ks[(nt * 8 + qr) * FSTR + ks * 8 + qc    ];
                float b1 = Ks[(nt * 8 + qr) * FSTR + ks * 8 + qc + 4];
                split_tf32(b0, bhi[nt][0], blo[nt][0]);
                split_tf32(b1, bhi[nt][1], blo[nt][1]);
            }
#pragma unroll
            for (int nt = 0; nt < 8; nt++) {
                mma_tf32(sa[nt], qhi[ks], blo[nt]);
                mma_tf32(sa[nt], qlo[ks], bhi[nt]);
                mma_tf32(sa[nt], qhi[ks], bhi[nt]);
            }
        }

        if (diag) {
#pragma unroll
            for (int nt = 0; nt < 8; nt++)
#pragma unroll
                for (int r = 0; r < 4; r++) {
                    int row = wrow + qr + ((r >> 1) << 3);
                    int col = nt * 8 + 2 * qc + (r & 1);
                    if (col > row) sa[nt][r] = -INFINITY;
                }
        }

        // online softmax (rows qr -> half0, qr+8 -> half1)
        float mx0 = -INFINITY, mx1 = -INFINITY;
#pragma unroll
        for (int nt = 0; nt < 8; nt++) {
            mx0 = fmaxf(mx0, fmaxf(sa[nt][0], sa[nt][1]));
            mx1 = fmaxf(mx1, fmaxf(sa[nt][2], sa[nt][3]));
        }
        mx0 = fmaxf(mx0, __shfl_xor_sync(0xffffffffu, mx0, 1));
        mx0 = fmaxf(mx0, __shfl_xor_sync(0xffffffffu, mx0, 2));
        mx1 = fmaxf(mx1, __shfl_xor_sync(0xffffffffu, mx1, 1));
        mx1 = fmaxf(mx1, __shfl_xor_sync(0xffffffffu, mx1, 2));

        float mn0 = fmaxf(m0, mx0), mn1 = fmaxf(m1, mx1);
        float c0 = __expf(m0 - mn0), c1 = __expf(m1 - mn1);

        float rs0 = 0.f, rs1 = 0.f;
#pragma unroll
        for (int nt = 0; nt < 8; nt++) {
            float p0 = __expf(sa[nt][0] - mn0);
            float p1 = __expf(sa[nt][1] - mn0);
            float p2 = __expf(sa[nt][2] - mn1);
            float p3 = __expf(sa[nt][3] - mn1);
            rs0 += p0 + p1; rs1 += p2 + p3;
            QP[(wrow + qr    ) * FSTR + nt * 8 + 2 * qc    ] = p0;
            QP[(wrow + qr    ) * FSTR + nt * 8 + 2 * qc + 1] = p1;
            QP[(wrow + qr + 8) * FSTR + nt * 8 + 2 * qc    ] = p2;
            QP[(wrow + qr + 8) * FSTR + nt * 8 + 2 * qc + 1] = p3;
        }
        rs0 += __shfl_xor_sync(0xffffffffu, rs0, 1);
        rs0 += __shfl_xor_sync(0xffffffffu, rs0, 2);
        rs1 += __shfl_xor_sync(0xffffffffu, rs1, 1);
        rs1 += __shfl_xor_sync(0xffffffffu, rs1, 2);

        l0 = l0 * c0 + rs0; l1 = l1 * c1 + rs1;
        m0 = mn0; m1 = mn1;
#pragma unroll
        for (int nt = 0; nt < 8; nt++) {
            oa[nt][0] *= c0; oa[nt][1] *= c0;
            oa[nt][2] *= c1; oa[nt][3] *= c1;
        }

        __syncwarp();   // P rows are warp-private; warp-level visibility is enough

        // O += P @ V
#pragma unroll
        for (int ks = 0; ks < 8; ks++) {
            float a0 = QP[(wrow + qr    ) * FSTR + ks * 8 + qc    ];
            float a1 = QP[(wrow + qr + 8) * FSTR + ks * 8 + qc    ];
            float a2 = QP[(wrow + qr    ) * FSTR + ks * 8 + qc + 4];
            float a3 = QP[(wrow + qr + 8) * FSTR + ks * 8 + qc + 4];
            uint32_t phi[4], plo[4];
            split_tf32(a0, phi[0], plo[0]);
            split_tf32(a1, phi[1], plo[1]);
            split_tf32(a2, phi[2], plo[2]);
            split_tf32(a3, phi[3], plo[3]);
#pragma unroll
            for (int nt = 0; nt < 8; nt++) {
                uint32_t vhi[2], vlo[2];
                float b0 = Vs[(ks * 8 + qc    ) * FSTR + nt * 8 + qr];
                float b1 = Vs[(ks * 8 + qc + 4) * FSTR + nt * 8 + qr];
                split_tf32(b0, vhi[0], vlo[0]);
                split_tf32(b1, vhi[1], vlo[1]);
                mma_tf32(oa[nt], phi, vlo);
                mma_tf32(oa[nt], plo, vhi);
                mma_tf32(oa[nt], phi, vhi);
            }
        }
    }

    // epilogue: O /= l, write [T, H, HD]
    float inv0 = 1.f / l0, inv1 = 1.f / l1;
    float* Ob = Om + ((size_t)(b * S_ + q0)) * D_ + h * HD_;
#pragma unroll
    for (int nt = 0; nt < 8; nt++) {
        int col = nt * 8 + 2 * qc;
        *(float2*)(Ob + (size_t)(wrow + qr) * D_ + col) =
            make_float2(oa[nt][0] * inv0, oa[nt][1] * inv0);
        *(float2*)(Ob + (size_t)(wrow + qr + 8) * D_ + col) =
            make_float2(oa[nt][2] * inv1, oa[nt][3] * inv1);
    }
}

// ---------------- SwiGLU: f0 = silu(f0) * f1 -------------------------------
__global__ void silu_mul_kernel() {
    int idx = blockIdx.x * blockDim.x + threadIdx.x;
    if (idx >= T_ * FF_) return;
    float a = g_f0[idx];
    float b = g_f1[idx];
    g_f0[idx] = a / (1.0f + expf(-a)) * b;
}

// ---------------- Launch ----------------------------------------------------
extern "C" void kernel_launch(void* const* d_in, const int* in_sizes, int n_in,
                              void* d_out, int out_size) {
    const float* x  = (const float*)d_in[0];
    const float* Wq = (const float*)d_in[1];
    const float* Wk = (const float*)d_in[2];
    const float* Wv = (const float*)d_in[3];
    const float* Wo = (const float*)d_in[4];
    const float* an = (const float*)d_in[5];
    const float* w0 = (const float*)d_in[6];
    const float* w1 = (const float*)d_in[7];
    const float* w2 = (const float*)d_in[8];
    const float* sn = (const float*)d_in[9];
    const float* on = (const float*)d_in[10];
    float* out = (float*)d_out;

    float *px, *ph, *pq, *pk, *pvv, *pattn, *pf0, *pf1;
    cudaGetSymbolAddress((void**)&px,    g_x);
    cudaGetSymbolAddress((void**)&ph,    g_h);
    cudaGetSymbolAddress((void**)&pq,    g_q);
    cudaGetSymbolAddress((void**)&pk,    g_kbuf);
    cudaGetSymbolAddress((void**)&pvv,   g_vbuf);
    cudaGetSymbolAddress((void**)&pattn, g_attn);
    cudaGetSymbolAddress((void**)&pf0,   g_f0);
    cudaGetSymbolAddress((void**)&pf1,   g_f1);

    cudaFuncSetAttribute(flash_kernel,
                         cudaFuncAttributeMaxDynamicSharedMemorySize, FSMEM_BYTES);

    rope_table_kernel<<<(S_*HALF_HD_ + 255)/256, 256>>>();

    for (int i = 0; i < L_; i++) {
        const float* xin = (i == 0) ? x : px;

        // attn-norm
        rmsnorm_kernel<<<T_, 256>>>(xin, an + (size_t)i * D_, ph);

        // QKV projections
        mma_gemm<128,128,16,32,64,0><<<dim3(D_/128, T_/128), 256>>>(
            ph, Wq + (size_t)i*D_*D_, nullptr, pq, D_, D_, D_, D_);
        mma_gemm<128,128,16,32,64,0><<<dim3((KVH_*HD_)/128, T_/128), 256>>>(
            ph, Wk + (size_t)i*D_*(KVH_*HD_), nullptr, pk,
            D_, D_, KVH_*HD_, KVH_*HD_);
        mma_gemm<128,128,16,32,64,0><<<dim3((KVH_*HD_)/128, T_/128), 256>>>(
            ph, Wv + (size_t)i*D_*(KVH_*HD_), nullptr, pvv,
            D_, D_, KVH_*HD_, KVH_*HD_);

        // RoPE on q, k
        {
            int tq = T_ * H_ * HALF_HD_;
            rope_kernel<<<(tq + 255)/256, 256>>>(pq, H_, tq);
            int tk = T_ * KVH_ * HALF_HD_;
            rope_kernel<<<(tk + 255)/256, 256>>>(pk, KVH_, tk);
        }

        // fused flash attention
        flash_kernel<<<dim3(S_/BMF, B_*H_), 128, FSMEM_BYTES>>>(pq, pk, pvv, pattn);

        // h2 = x + attn @ Wo
        mma_gemm<128,128,16,32,64,1><<<dim3(D_/128, T_/128), 256>>>(
            pattn, Wo + (size_t)i*D_*D_, xin, px, D_, D_, D_, D_);

        // ffn-norm
        rmsnorm_kernel<<<T_, 256>>>(px, sn + (size_t)i * D_, ph);

        // FFN
        mma_gemm<128,128,16,32,64,0><<<dim3(FF_/128, T_/128), 256>>>(
            ph, w0 + (size_t)i*D_*FF_, nullptr, pf0, D_, D_, FF_, FF_);
        mma_gemm<128,128,16,32,64,0><<<dim3(FF_/128, T_/128), 256>>>(
            ph, w1 + (size_t)i*D_*FF_, nullptr, pf1, D_, D_, FF_, FF_);
        silu_mul_kernel<<<(T_*FF_ + 255)/256, 256>>>();
        mma_gemm<128,128,16,32,64,1><<<dim3(D_/128, T_/128), 256>>>(
            pf0, w2 + (size_t)i*FF_*D_, px, px, FF_, FF_, D_, D_);
    }

    // final norm
    rmsnorm_kernel<<<T_, 256>>>(px, on, out);
}

// round 11
// speedup vs baseline: 1.4938x; 1.0251x over previous
#include <cuda_runtime.h>
#include <math.h>
#include <stdint.h>

// Problem constants
#define L_    2
#define B_    2
#define S_    2048
#define D_    768
#define H_    12
#define KVH_  4
#define HD_   64
#define NREP_ 3
#define FF_   3072
#define T_    (B_*S_)          // 4096 tokens
#define HALF_HD_ 32

// Flash tile config
#define BMF 64
#define BNF 64
#define FPAD 4
#define FSTR (BNF + FPAD)                 // 68 floats per row
#define FSMEM_BYTES (3 * 64 * FSTR * 4)   // K + V + QP tiles = 52224 B

// GEMM smem config (dynamic): raw double-buffered + single hi/lo
#define GBM 128
#define GBN 128
#define GBK 16
#define GBKP (GBK + 4)     // 20
#define GBNP (GBN + 4)     // 132
#define G_RAWA (2 * GBM * GBKP)            // 5120 floats
#define G_RAWB (2 * GBK * GBNP)            // 4224
#define G_HA   (GBM * GBKP)                // 2560
#define G_HB   (GBK * GBNP)                // 2112
#define GSMEM_FLOATS (G_RAWA + G_RAWB + 2*G_HA + 2*G_HB)   // 18688
#define GSMEM_BYTES  (GSMEM_FLOATS * 4)                    // 74752

// ---------------- Scratch (device globals; no allocation allowed) ----------
__device__ float g_x[T_*D_];
__device__ float g_h[T_*D_];
__device__ float g_q[T_*D_];
__device__ float g_kbuf[T_*KVH_*HD_];
__device__ float g_vbuf[T_*KVH_*HD_];
__device__ float g_attn[T_*D_];
__device__ float g_f0[T_*FF_];
__device__ float g_f1[T_*FF_];
__device__ float g_ct[S_*HALF_HD_];
__device__ float g_st[S_*HALF_HD_];

// ---------------- RoPE tables ----------------------------------------------
__global__ void rope_table_kernel() {
    int idx = blockIdx.x * blockDim.x + threadIdx.x;
    if (idx >= S_ * HALF_HD_) return;
    int s = idx / HALF_HD_;
    int i = idx % HALF_HD_;
    double freq = exp(-log(10000.0) * (double)(2 * i) / (double)HD_);
    float ff = (float)freq;
    float ang = (float)s * ff;
    g_ct[idx] = (float)cos((double)ang);
    g_st[idx] = (float)sin((double)ang);
}

// ---------------- RMSNorm ---------------------------------------------------
__global__ void rmsnorm_kernel(const float* __restrict__ in,
                               const float* __restrict__ w,
                               float* __restrict__ out) {
    int row = blockIdx.x;
    int tid = threadIdx.x;
    const float* p = in + (size_t)row * D_;
    float v0 = p[tid], v1 = p[tid + 256], v2 = p[tid + 512];
    float ss = v0 * v0 + v1 * v1 + v2 * v2;
    __shared__ float red[256];
    red[tid] = ss;
    __syncthreads();
    for (int o = 128; o > 0; o >>= 1) {
        if (tid < o) red[tid] += red[tid + o];
        __syncthreads();
    }
    float inv = rsqrtf(red[0] * (1.0f / (float)D_) + 1e-6f);
    float* q = out + (size_t)row * D_;
    q[tid]       = v0 * inv * w[tid];
    q[tid + 256] = v1 * inv * w[tid + 256];
    q[tid + 512] = v2 * inv * w[tid + 512];
}

// ---------------- RoPE (in place) -------------------------------------------
__global__ void rope_kernel(float* __restrict__ t, int nh, int total) {
    int idx = blockIdx.x * blockDim.x + threadIdx.x;
    if (idx >= total) return;
    int i   = idx % HALF_HD_;
    int hh  = (idx / HALF_HD_) % nh;
    int row = idx / (HALF_HD_ * nh);
    int s   = row % S_;
    float c  = g_ct[s * HALF_HD_ + i];
    float sn = g_st[s * HALF_HD_ + i];
    size_t base = ((size_t)row * nh + hh) * HD_ + 2 * i;
    float t0 = t[base], t1 = t[base + 1];
    t[base]     = t0 * c - t1 * sn;
    t[base + 1] = t0 * sn + t1 * c;
}

// ---------------- tf32 helpers ----------------------------------------------
__device__ __forceinline__ void split_tf32(float x, uint32_t& hi, uint32_t& lo) {
    uint32_t h;
    asm("cvt.rna.tf32.f32 %0, %1;" : "=r"(h) : "f"(x));
    float hf = __uint_as_float(h);
    float l = x - hf;
    uint32_t lw;
    asm("cvt.rna.tf32.f32 %0, %1;" : "=r"(lw) : "f"(l));
    hi = h; lo = lw;
}

__device__ __forceinline__ void mma_tf32(float* c, const uint32_t* a, const uint32_t* b) {
    asm volatile(
        "mma.sync.aligned.m16n8k8.row.col.f32.tf32.tf32.f32 "
        "{%0,%1,%2,%3}, {%4,%5,%6,%7}, {%8,%9}, {%0,%1,%2,%3};"
        : "+f"(c[0]), "+f"(c[1]), "+f"(c[2]), "+f"(c[3])
        : "r"(a[0]), "r"(a[1]), "r"(a[2]), "r"(a[3]), "r"(b[0]), "r"(b[1]));
}

// ---------------- Tensor-core GEMM (tf32 x3, smem-resident splits) ----------
// MODE 0: C = A @ B
// MODE 1: C = A @ B + R
// MODE 5: fused QKV — n-blocks 0..5 -> Bm/C (768), 6..7 -> B2/C2 (256), 8..9 -> B3/C3 (256)
template<int MODE>
__global__ void __launch_bounds__(256, 2)
mma_gemm(const float* __restrict__ A, const float* __restrict__ Bm,
         const float* __restrict__ R, float* __restrict__ C,
         int K, int lda, int ldb, int ldc,
         const float* __restrict__ B2, const float* __restrict__ B3,
         float* __restrict__ C2, float* __restrict__ C3)
{
    constexpr int BM = GBM, BN = GBN, BK = GBK;
    constexpr int WM = 32, WN = 64;
    const int m0 = blockIdx.y * BM;
    int n0 = blockIdx.x * BN;

    if (MODE == 5) {
        int nb = blockIdx.x;
        if (nb >= 6) {
            if (nb >= 8) { Bm = B3; C = C3; nb -= 8; }
            else         { Bm = B2; C = C2; nb -= 6; }
            ldb = KVH_ * HD_; ldc = KVH_ * HD_;
        }
        n0 = nb * BN;
    }
    const int nk = K / BK;

    extern __shared__ __align__(16) float dsm[];
    float* rawA = dsm;                       // [2][BM][GBKP]
    float* rawB = rawA + G_RAWA;             // [2][BK][GBNP]
    float* hiA  = rawB + G_RAWB;             // [BM][GBKP]
    float* loA  = hiA + G_HA;
    float* hiB  = loA + G_HA;                // [BK][GBNP]
    float* loB  = hiB + G_HB;

    const int tid  = threadIdx.x;
    const int lane = tid & 31;
    const int warp = tid >> 5;
    const int wm = warp & 3;            // 4 warps along M
    const int wn = warp >> 2;           // 2 along N
    constexpr int MT  = WM / 16;        // 2
    constexpr int NT2 = WN / 8;         // 8

    const int qr = lane >> 2;
    const int qc = lane & 3;

    float acc[MT][NT2][4];
#pragma unroll
    for (int mt = 0; mt < MT; mt++)
#pragma unroll
        for (int nt = 0; nt < NT2; nt++)
#pragma unroll
            for (int r = 0; r < 4; r++) acc[mt][nt][r] = 0.0f;

    auto loadA = [&](int kt, int s) {
#pragma unroll
        for (int i = 0; i < 2; i++) {                 // BM*BK/4/256 = 2
            int ch  = tid + i * 256;
            int row = ch / (BK / 4);
            int kq  = (ch % (BK / 4)) * 4;
            const float* src = A + (size_t)(m0 + row) * lda + kt * BK + kq;
            uint32_t dst = (uint32_t)__cvta_generic_to_shared(
                &rawA[s * BM * GBKP + row * GBKP + kq]);
            asm volatile("cp.async.cg.shared.global [%0], [%1], 16;" :: "r"(dst), "l"(src));
        }
    };
    auto loadB = [&](int kt, int s) {
#pragma unroll
        for (int i = 0; i < 2; i++) {                 // BK*BN/4/256 = 2
            int ch  = tid + i * 256;
            int row = ch / (BN / 4);
            int cq  = (ch % (BN / 4)) * 4;
            const float* src = Bm + (size_t)(kt * BK + row) * ldb + n0 + cq;
            uint32_t dst = (uint32_t)__cvta_generic_to_shared(
                &rawB[s * BK * GBNP + row * GBNP + cq]);
            asm volatile("cp.async.cg.shared.global [%0], [%1], 16;" :: "r"(dst), "l"(src));
        }
    };

    loadA(0, 0); loadB(0, 0);
    asm volatile("cp.async.commit_group;");

    for (int kt = 0; kt < nk; kt++) {
        const int s = kt & 1;
        if (kt + 1 < nk) {
            loadA(kt + 1, s ^ 1); loadB(kt + 1, s ^ 1);
            asm volatile("cp.async.commit_group;");
            asm volatile("cp.async.wait_group 1;");
        } else {
            asm volatile("cp.async.wait_group 0;");
        }
        __syncthreads();   // raw(kt) ready; hi/lo free of previous consumers

        // Cooperative split pass: raw -> hi/lo (each element split exactly once)
#pragma unroll
        for (int i = 0; i < 2; i++) {
            int ch  = tid + i * 256;
            int row = ch / (BK / 4);
            int kq  = (ch % (BK / 4)) * 4;
            float4 v = *(float4*)&rawA[s * BM * GBKP + row * GBKP + kq];
            uint32_t h0,l0,h1,l1,h2,l2,h3,l3;
            split_tf32(v.x, h0, l0); split_tf32(v.y, h1, l1);
            split_tf32(v.z, h2, l2); split_tf32(v.w, h3, l3);
            float4 hv = make_float4(__uint_as_float(h0), __uint_as_float(h1),
                                    __uint_as_float(h2), __uint_as_float(h3));
            float4 lv = make_float4(__uint_as_float(l0), __uint_as_float(l1),
                                    __uint_as_float(l2), __uint_as_float(l3));
            *(float4*)&hiA[row * GBKP + kq] = hv;
            *(float4*)&loA[row * GBKP + kq] = lv;
        }
#pragma unroll
        for (int i = 0; i < 2; i++) {
            int ch  = tid + i * 256;
            int row = ch / (BN / 4);
            int cq  = (ch % (BN / 4)) * 4;
            float4 v = *(float4*)&rawB[s * BK * GBNP + row * GBNP + cq];
            uint32_t h0,l0,h1,l1,h2,l2,h3,l3;
            split_tf32(v.x, h0, l0); split_tf32(v.y, h1, l1);
            split_tf32(v.z, h2, l2); split_tf32(v.w, h3, l3);
            float4 hv = make_float4(__uint_as_float(h0), __uint_as_float(h1),
                                    __uint_as_float(h2), __uint_as_float(h3));
            float4 lv = make_float4(__uint_as_float(l0), __uint_as_float(l1),
                                    __uint_as_float(l2), __uint_as_float(l3));
            *(float4*)&hiB[row * GBNP + cq] = hv;
            *(float4*)&loB[row * GBNP + cq] = lv;
        }
        __syncthreads();   // hi/lo ready

        // Pure LDS + MMA inner loop
#pragma unroll
        for (int ks = 0; ks < BK; ks += 8) {
            uint32_t ahi[MT][4], alo[MT][4];
#pragma unroll
            for (int mt = 0; mt < MT; mt++) {
                int m = wm * WM + mt * 16 + qr;
                ahi[mt][0] = __float_as_uint(hiA[(m    ) * GBKP + ks + qc]);
                ahi[mt][1] = __float_as_uint(hiA[(m + 8) * GBKP + ks + qc]);
                ahi[mt][2] = __float_as_uint(hiA[(m    ) * GBKP + ks + qc + 4]);
                ahi[mt][3] = __float_as_uint(hiA[(m + 8) * GBKP + ks + qc + 4]);
                alo[mt][0] = __float_as_uint(loA[(m    ) * GBKP + ks + qc]);
                alo[mt][1] = __float_as_uint(loA[(m + 8) * GBKP + ks + qc]);
                alo[mt][2] = __float_as_uint(loA[(m    ) * GBKP + ks + qc + 4]);
                alo[mt][3] = __float_as_uint(loA[(m + 8) * GBKP + ks + qc + 4]);
            }
#pragma unroll
            for (int nt = 0; nt < NT2; nt++) {
                int n = wn * WN + nt * 8 + qr;
                uint32_t bhi[2], blo[2];
                bhi[0] = __float_as_uint(hiB[(ks + qc    ) * GBNP + n]);
                bhi[1] = __float_as_uint(hiB[(ks + qc + 4) * GBNP + n]);
                blo[0] = __float_as_uint(loB[(ks + qc    ) * GBNP + n]);
                blo[1] = __float_as_uint(loB[(ks + qc + 4) * GBNP + n]);
#pragma unroll
                for (int mt = 0; mt < MT; mt++) {
                    mma_tf32(acc[mt][nt], ahi[mt], blo);
                    mma_tf32(acc[mt][nt], alo[mt], bhi);
                    mma_tf32(acc[mt][nt], ahi[mt], bhi);
                }
            }
        }
    }

#pragma unroll
    for (int mt = 0; mt < MT; mt++)
#pragma unroll
        for (int nt = 0; nt < NT2; nt++) {
            int m = m0 + wm * WM + mt * 16 + qr;
            int n = n0 + wn * WN + nt * 8 + 2 * qc;
            size_t o0 = (size_t)m * ldc + n;
            size_t o1 = (size_t)(m + 8) * ldc + n;
            float2 v0 = make_float2(acc[mt][nt][0], acc[mt][nt][1]);
            float2 v1 = make_float2(acc[mt][nt][2], acc[mt][nt][3]);
            if (MODE == 1) {
                v0.x += R[o0]; v0.y += R[o0 + 1];
                v1.x += R[o1]; v1.y += R[o1 + 1];
            }
            *(float2*)(C + o0) = v0;
            *(float2*)(C + o1) = v1;
        }
}

// ---------------- Fused flash attention (tf32x3, online softmax) ------------
__global__ void __launch_bounds__(128)
flash_kernel(const float* __restrict__ Qm, const float* __restrict__ Km,
             const float* __restrict__ Vm, float* __restrict__ Om) {
    extern __shared__ __align__(16) float fsm[];
    float* Ks = fsm;
    float* Vs = fsm + 64 * FSTR;
    float* QP = fsm + 2 * 64 * FSTR;

    const int z = blockIdx.y;
    const int b = z / H_, h = z % H_, kvh = h / NREP_;
    const int q0 = ((int)gridDim.x - 1 - (int)blockIdx.x) * BMF;

    const int tid  = threadIdx.x;
    const int lane = tid & 31;
    const int warp = tid >> 5;
    const int qr = lane >> 2, qc = lane & 3;
    const int wrow = warp * 16;

    const float* Qb = Qm + ((size_t)(b * S_ + q0)) * D_ + h * HD_;
    const float* Kb = Km + ((size_t)b * S_) * (KVH_ * HD_) + kvh * HD_;
    const float* Vb = Vm + ((size_t)b * S_) * (KVH_ * HD_) + kvh * HD_;

    for (int i = tid; i < 64 * 16; i += 128) {
        int r = i >> 4, cq = (i & 15) << 2;
        *(float4*)&QP[r * FSTR + cq] = *(const float4*)(Qb + (size_t)r * D_ + cq);
    }
    __syncthreads();

    uint32_t qhi[8][4], qlo[8][4];
#pragma unroll
    for (int ks = 0; ks < 8; ks++) {
        float a0 = QP[(wrow + qr    ) * FSTR + ks * 8 + qc    ] * 0.125f;
        float a1 = QP[(wrow + qr + 8) * FSTR + ks * 8 + qc    ] * 0.125f;
        float a2 = QP[(wrow + qr    ) * FSTR + ks * 8 + qc + 4] * 0.125f;
        float a3 = QP[(wrow + qr + 8) * FSTR + ks * 8 + qc + 4] * 0.125f;
        split_tf32(a0, qhi[ks][0], qlo[ks][0]);
        split_tf32(a1, qhi[ks][1], qlo[ks][1]);
        split_tf32(a2, qhi[ks][2], qlo[ks][2]);
        split_tf32(a3, qhi[ks][3], qlo[ks][3]);
    }

    float m0 = -INFINITY, m1 = -INFINITY, l0 = 0.f, l1 = 0.f;
    float oa[8][4];
#pragma unroll
    for (int nt = 0; nt < 8; nt++)
#pragma unroll
        for (int r = 0; r < 4; r++) oa[nt][r] = 0.f;

    const int niter = q0 / BNF + 1;
    for (int it = 0; it < niter; it++) {
        const int j0 = it * BNF;
        const bool diag = (j0 == q0);

        __syncthreads();
        for (int i = tid; i < 64 * 16; i += 128) {
            int r = i >> 4, cq = (i & 15) << 2;
            *(float4*)&Ks[r * FSTR + cq] =
                *(const float4*)(Kb + (size_t)(j0 + r) * (KVH_ * HD_) + cq);
            *(float4*)&Vs[r * FSTR + cq] =
                *(const float4*)(Vb + (size_t)(j0 + r) * (KVH_ * HD_) + cq);
        }
        __syncthreads();

        float sa[8][4];
#pragma unroll
        for (int nt = 0; nt < 8; nt++)
#pragma unroll
            for (int r = 0; r < 4; r++) sa[nt][r] = 0.f;

#pragma unroll
        for (int ks = 0; ks < 8; ks++) {
            uint32_t bhi[8][2], blo[8][2];
#pragma unroll
            for (int nt = 0; nt < 8; nt++) {
                float b0 = Ks[(nt * 8 + qr) * FSTR + ks * 8 + qc    ];
                float b1 = Ks[(nt * 8 + qr) * FSTR + ks * 8 + qc + 4];
                split_tf32(b0, bhi[nt][0], blo[nt][0]);
                split_tf32(b1, bhi[nt][1], blo[nt][1]);
            }
#pragma unroll
            for (int nt = 0; nt < 8; nt++) {
                mma_tf32(sa[nt], qhi[ks], blo[nt]);
                mma_tf32(sa[nt], qlo[ks], bhi[nt]);
                mma_tf32(sa[nt], qhi[ks], bhi[nt]);
            }
        }

        if (diag) {
#pragma unroll
            for (int nt = 0; nt < 8; nt++)
#pragma unroll
                for (int r = 0; r < 4; r++) {
                    int row = wrow + qr + ((r >> 1) << 3);
                    int col = nt * 8 + 2 * qc + (r & 1);
                    if (col > row) sa[nt][r] = -INFINITY;
                }
        }

        float mx0 = -INFINITY, mx1 = -INFINITY;
#pragma unroll
        for (int nt = 0; nt < 8; nt++) {
            mx0 = fmaxf(mx0, fmaxf(sa[nt][0], sa[nt][1]));
            mx1 = fmaxf(mx1, fmaxf(sa[nt][2], sa[nt][3]));
        }
        mx0 = fmaxf(mx0, __shfl_xor_sync(0xffffffffu, mx0, 1));
        mx0 = fmaxf(mx0, __shfl_xor_sync(0xffffffffu, mx0, 2));
        mx1 = fmaxf(mx1, __shfl_xor_sync(0xffffffffu, mx1, 1));
        mx1 = fmaxf(mx1, __shfl_xor_sync(0xffffffffu, mx1, 2));

        float mn0 = fmaxf(m0, mx0), mn1 = fmaxf(m1, mx1);
        float c0 = __expf(m0 - mn0), c1 = __expf(m1 - mn1);

        float rs0 = 0.f, rs1 = 0.f;
#pragma unroll
        for (int nt = 0; nt < 8; nt++) {
            float p0 = __expf(sa[nt][0] - mn0);
            float p1 = __expf(sa[nt][1] - mn0);
            float p2 = __expf(sa[nt][2] - mn1);
            float p3 = __expf(sa[nt][3] - mn1);
            rs0 += p0 + p1; rs1 += p2 + p3;
            QP[(wrow + qr    ) * FSTR + nt * 8 + 2 * qc    ] = p0;
            QP[(wrow + qr    ) * FSTR + nt * 8 + 2 * qc + 1] = p1;
            QP[(wrow + qr + 8) * FSTR + nt * 8 + 2 * qc    ] = p2;
            QP[(wrow + qr + 8) * FSTR + nt * 8 + 2 * qc + 1] = p3;
        }
        rs0 += __shfl_xor_sync(0xffffffffu, rs0, 1);
        rs0 += __shfl_xor_sync(0xffffffffu, rs0, 2);
        rs1 += __shfl_xor_sync(0xffffffffu, rs1, 1);
        rs1 += __shfl_xor_sync(0xffffffffu, rs1, 2);

        l0 = l0 * c0 + rs0; l1 = l1 * c1 + rs1;
        m0 = mn0; m1 = mn1;
#pragma unroll
        for (int nt = 0; nt < 8; nt++) {
            oa[nt][0] *= c0; oa[nt][1] *= c0;
            oa[nt][2] *= c1; oa[nt][3] *= c1;
        }

        __syncwarp();

#pragma unroll
        for (int ks = 0; ks < 8; ks++) {
            float a0 = QP[(wrow + qr    ) * FSTR + ks * 8 + qc    ];
            float a1 = QP[(wrow + qr + 8) * FSTR + ks * 8 + qc    ];
            float a2 = QP[(wrow + qr    ) * FSTR + ks * 8 + qc + 4];
            float a3 = QP[(wrow + qr + 8) * FSTR + ks * 8 + qc + 4];
            uint32_t phi[4], plo[4];
            split_tf32(a0, phi[0], plo[0]);
            split_tf32(a1, phi[1], plo[1]);
            split_tf32(a2, phi[2], plo[2]);
            split_tf32(a3, phi[3], plo[3]);
#pragma unroll
            for (int nt = 0; nt < 8; nt++) {
                uint32_t vhi[2], vlo[2];
                float b0 = Vs[(ks * 8 + qc    ) * FSTR + nt * 8 + qr];
                float b1 = Vs[(ks * 8 + qc + 4) * FSTR + nt * 8 + qr];
                split_tf32(b0, vhi[0], vlo[0]);
                split_tf32(b1, vhi[1], vlo[1]);
                mma_tf32(oa[nt], phi, vlo);
                mma_tf32(oa[nt], plo, vhi);
                mma_tf32(oa[nt], phi, vhi);
            }
        }
    }

    float inv0 = 1.f / l0, inv1 = 1.f / l1;
    float* Ob = Om + ((size_t)(b * S_ + q0)) * D_ + h * HD_;
#pragma unroll
    for (int nt = 0; nt < 8; nt++) {
        int col = nt * 8 + 2 * qc;
        *(float2*)(Ob + (size_t)(wrow + qr) * D_ + col) =
            make_float2(oa[nt][0] * inv0, oa[nt][1] * inv0);
        *(float2*)(Ob + (size_t)(wrow + qr + 8) * D_ + col) =
            make_float2(oa[nt][2] * inv1, oa[nt][3] * inv1);
    }
}

// ---------------- SwiGLU: f0 = silu(f0) * f1 -------------------------------
__global__ void silu_mul_kernel() {
    int idx = blockIdx.x * blockDim.x + threadIdx.x;
    if (idx >= T_ * FF_) return;
    float a = g_f0[idx];
    float b = g_f1[idx];
    g_f0[idx] = a / (1.0f + expf(-a)) * b;
}

// ---------------- Launch ----------------------------------------------------
extern "C" void kernel_launch(void* const* d_in, const int* in_sizes, int n_in,
                              void* d_out, int out_size) {
    const float* x  = (const float*)d_in[0];
    const float* Wq = (const float*)d_in[1];
    const float* Wk = (const float*)d_in[2];
    const float* Wv = (const float*)d_in[3];
    const float* Wo = (const float*)d_in[4];
    const float* an = (const float*)d_in[5];
    const float* w0 = (const float*)d_in[6];
    const float* w1 = (const float*)d_in[7];
    const float* w2 = (const float*)d_in[8];
    const float* sn = (const float*)d_in[9];
    const float* on = (const float*)d_in[10];
    float* out = (float*)d_out;

    float *px, *ph, *pq, *pk, *pvv, *pattn, *pf0, *pf1;
    cudaGetSymbolAddress((void**)&px,    g_x);
    cudaGetSymbolAddress((void**)&ph,    g_h);
    cudaGetSymbolAddress((void**)&pq,    g_q);
    cudaGetSymbolAddress((void**)&pk,    g_kbuf);
    cudaGetSymbolAddress((void**)&pvv,   g_vbuf);
    cudaGetSymbolAddress((void**)&pattn, g_attn);
    cudaGetSymbolAddress((void**)&pf0,   g_f0);
    cudaGetSymbolAddress((void**)&pf1,   g_f1);

    cudaFuncSetAttribute(flash_kernel,
                         cudaFuncAttributeMaxDynamicSharedMemorySize, FSMEM_BYTES);
    cudaFuncSetAttribute(mma_gemm<0>,
                         cudaFuncAttributeMaxDynamicSharedMemorySize, GSMEM_BYTES);
    cudaFuncSetAttribute(mma_gemm<1>,
                         cudaFuncAttributeMaxDynamicSharedMemorySize, GSMEM_BYTES);
    cudaFuncSetAttribute(mma_gemm<5>,
                         cudaFuncAttributeMaxDynamicSharedMemorySize, GSMEM_BYTES);

    rope_table_kernel<<<(S_*HALF_HD_ + 255)/256, 256>>>();

    for (int i = 0; i < L_; i++) {
        const float* xin = (i == 0) ? x : px;

        rmsnorm_kernel<<<T_, 256>>>(xin, an + (size_t)i * D_, ph);

        // fused QKV projection: one launch, grid (6+2+2, 32)
        mma_gemm<5><<<dim3(10, T_/128), 256, GSMEM_BYTES>>>(
            ph, Wq + (size_t)i*D_*D_, nullptr, pq, D_, D_, D_, D_,
            Wk + (size_t)i*D_*(KVH_*HD_), Wv + (size_t)i*D_*(KVH_*HD_), pk, pvv);

        {
            int tq = T_ * H_ * HALF_HD_;
            rope_kernel<<<(tq + 255)/256, 256>>>(pq, H_, tq);
            int tk = T_ * KVH_ * HALF_HD_;
            rope_kernel<<<(tk + 255)/256, 256>>>(pk, KVH_, tk);
        }

        flash_kernel<<<dim3(S_/BMF, B_*H_), 128, FSMEM_BYTES>>>(pq, pk, pvv, pattn);

        mma_gemm<1><<<dim3(D_/128, T_/128), 256, GSMEM_BYTES>>>(
            pattn, Wo + (size_t)i*D_*D_, xin, px, D_, D_, D_, D_,
            nullptr, nullptr, nullptr, nullptr);

        rmsnorm_kernel<<<T_, 256>>>(px, sn + (size_t)i * D_, ph);

        mma_gemm<0><<<dim3(FF_/128, T_/128), 256, GSMEM_BYTES>>>(
            ph, w0 + (size_t)i*D_*FF_, nullptr, pf0, D_, D_, FF_, FF_,
            nullptr, nullptr, nullptr, nullptr);
        mma_gemm<0><<<dim3(FF_/128, T_/128), 256, GSMEM_BYTES>>>(
            ph, w1 + (size_t)i*D_*FF_, nullptr, pf1, D_, D_, FF_, FF_,
            nullptr, nullptr, nullptr, nullptr);
        silu_mul_kernel<<<(T_*FF_ + 255)/256, 256>>>();
        mma_gemm<1><<<dim3(D_/128, T_/128), 256, GSMEM_BYTES>>>(
            pf0, w2 + (size_t)i*FF_*D_, px, px, FF_, FF_, D_, D_,
            nullptr, nullptr, nullptr, nullptr);
    }

    rmsnorm_kernel<<<T_, 256>>>(px, on, out);
}

// round 12
// speedup vs baseline: 2.0513x; 1.3732x over previous
#include <cuda_runtime.h>
#include <cuda_bf16.h>
#include <math.h>
#include <stdint.h>

// Problem constants
#define L_    2
#define B_    2
#define S_    2048
#define D_    768
#define H_    12
#define KVH_  4
#define HD_   64
#define NREP_ 3
#define FF_   3072
#define T_    (B_*S_)          // 4096 tokens
#define HALF_HD_ 32

// Flash tile config
#define BMF 64
#define BNF 64
#define FPAD 4
#define FSTR (BNF + FPAD)                 // 68 floats per row
#define FSMEM_BYTES (3 * 64 * FSTR * 4)   // K + V + QP tiles = 52224 B

// GEMM smem config (dynamic)
#define GBM 128
#define GBN 128
#define GBK 16
#define GBKH 8             // k-pairs per tile
#define GPS 12             // packed row stride in uint32 (conflict-free: qr*12+qc)
#define GBKP (GBK + 4)     // 20
#define GBNP (GBN + 4)     // 132
#define G_RAWA (2 * GBM * GBKP)            // 5120 floats
#define G_RAWB (2 * GBK * GBNP)            // 4224 floats
#define G_PA   (GBM * GPS)                 // 1536 uint32
#define G_PB   (GBN * GPS)                 // 1536 uint32
#define GSMEM_BYTES ((G_RAWA + G_RAWB) * 4 + 4 * G_PA * 4)   // 61952 B

// ---------------- Scratch (device globals; no allocation allowed) ----------
__device__ float g_x[T_*D_];
__device__ float g_h[T_*D_];
__device__ float g_q[T_*D_];
__device__ float g_kbuf[T_*KVH_*HD_];
__device__ float g_vbuf[T_*KVH_*HD_];
__device__ float g_attn[T_*D_];
__device__ float g_f0[T_*FF_];
__device__ float g_f1[T_*FF_];
__device__ float g_ct[S_*HALF_HD_];
__device__ float g_st[S_*HALF_HD_];

// ---------------- RoPE tables ----------------------------------------------
__global__ void rope_table_kernel() {
    int idx = blockIdx.x * blockDim.x + threadIdx.x;
    if (idx >= S_ * HALF_HD_) return;
    int s = idx / HALF_HD_;
    int i = idx % HALF_HD_;
    double freq = exp(-log(10000.0) * (double)(2 * i) / (double)HD_);
    float ff = (float)freq;
    float ang = (float)s * ff;
    g_ct[idx] = (float)cos((double)ang);
    g_st[idx] = (float)sin((double)ang);
}

// ---------------- RMSNorm ---------------------------------------------------
__global__ void rmsnorm_kernel(const float* __restrict__ in,
                               const float* __restrict__ w,
                               float* __restrict__ out) {
    int row = blockIdx.x;
    int tid = threadIdx.x;
    const float* p = in + (size_t)row * D_;
    float v0 = p[tid], v1 = p[tid + 256], v2 = p[tid + 512];
    float ss = v0 * v0 + v1 * v1 + v2 * v2;
    __shared__ float red[256];
    red[tid] = ss;
    __syncthreads();
    for (int o = 128; o > 0; o >>= 1) {
        if (tid < o) red[tid] += red[tid + o];
        __syncthreads();
    }
    float inv = rsqrtf(red[0] * (1.0f / (float)D_) + 1e-6f);
    float* q = out + (size_t)row * D_;
    q[tid]       = v0 * inv * w[tid];
    q[tid + 256] = v1 * inv * w[tid + 256];
    q[tid + 512] = v2 * inv * w[tid + 512];
}

// ---------------- RoPE (in place) -------------------------------------------
__global__ void rope_kernel(float* __restrict__ t, int nh, int total) {
    int idx = blockIdx.x * blockDim.x + threadIdx.x;
    if (idx >= total) return;
    int i   = idx % HALF_HD_;
    int hh  = (idx / HALF_HD_) % nh;
    int row = idx / (HALF_HD_ * nh);
    int s   = row % S_;
    float c  = g_ct[s * HALF_HD_ + i];
    float sn = g_st[s * HALF_HD_ + i];
    size_t base = ((size_t)row * nh + hh) * HD_ + 2 * i;
    float t0 = t[base], t1 = t[base + 1];
    t[base]     = t0 * c - t1 * sn;
    t[base + 1] = t0 * sn + t1 * c;
}

// ---------------- numeric helpers -------------------------------------------
__device__ __forceinline__ void split_tf32(float x, uint32_t& hi, uint32_t& lo) {
    uint32_t h;
    asm("cvt.rna.tf32.f32 %0, %1;" : "=r"(h) : "f"(x));
    float hf = __uint_as_float(h);
    float l = x - hf;
    uint32_t lw;
    asm("cvt.rna.tf32.f32 %0, %1;" : "=r"(lw) : "f"(l));
    hi = h; lo = lw;
}

__device__ __forceinline__ void mma_tf32(float* c, const uint32_t* a, const uint32_t* b) {
    asm volatile(
        "mma.sync.aligned.m16n8k8.row.col.f32.tf32.tf32.f32 "
        "{%0,%1,%2,%3}, {%4,%5,%6,%7}, {%8,%9}, {%0,%1,%2,%3};"
        : "+f"(c[0]), "+f"(c[1]), "+f"(c[2]), "+f"(c[3])
        : "r"(a[0]), "r"(a[1]), "r"(a[2]), "r"(a[3]), "r"(b[0]), "r"(b[1]));
}

__device__ __forceinline__ void mma_bf16(float* c, const uint32_t* a, const uint32_t* b) {
    asm volatile(
        "mma.sync.aligned.m16n8k16.row.col.f32.bf16.bf16.f32 "
        "{%0,%1,%2,%3}, {%4,%5,%6,%7}, {%8,%9}, {%0,%1,%2,%3};"
        : "+f"(c[0]), "+f"(c[1]), "+f"(c[2]), "+f"(c[3])
        : "r"(a[0]), "r"(a[1]), "r"(a[2]), "r"(a[3]), "r"(b[0]), "r"(b[1]));
}

// Split two fp32 into bf16 hi/lo, packed along k (x0 -> low half).
__device__ __forceinline__ void split_pack_bf16(float x0, float x1,
                                                uint32_t& hi, uint32_t& lo) {
    __nv_bfloat16 h0 = __float2bfloat16_rn(x0);
    __nv_bfloat16 h1 = __float2bfloat16_rn(x1);
    __nv_bfloat16 l0 = __float2bfloat16_rn(x0 - __bfloat162float(h0));
    __nv_bfloat16 l1 = __float2bfloat16_rn(x1 - __bfloat162float(h1));
    hi = (uint32_t)__bfloat16_as_ushort(h0) | ((uint32_t)__bfloat16_as_ushort(h1) << 16);
    lo = (uint32_t)__bfloat16_as_ushort(l0) | ((uint32_t)__bfloat16_as_ushort(l1) << 16);
}

// ---------------- Tensor-core GEMM (bf16 x3 split, m16n8k16) ----------------
// MODE 0: C = A @ B
// MODE 1: C = A @ B + R
// MODE 5: fused QKV — n-blocks 0..5 -> Bm/C (768), 6..7 -> B2/C2, 8..9 -> B3/C3
template<int MODE>
__global__ void __launch_bounds__(256, 2)
mma_gemm(const float* __restrict__ A, const float* __restrict__ Bm,
         const float* __restrict__ R, float* __restrict__ C,
         int K, int lda, int ldb, int ldc,
         const float* __restrict__ B2, const float* __restrict__ B3,
         float* __restrict__ C2, float* __restrict__ C3)
{
    constexpr int BM = GBM, BN = GBN, BK = GBK;
    const int m0 = blockIdx.y * BM;
    int n0 = blockIdx.x * BN;

    if (MODE == 5) {
        int nb = blockIdx.x;
        if (nb >= 6) {
            if (nb >= 8) { Bm = B3; C = C3; nb -= 8; }
            else         { Bm = B2; C = C2; nb -= 6; }
            ldb = KVH_ * HD_; ldc = KVH_ * HD_;
        }
        n0 = nb * BN;
    }
    const int nk = K / BK;

    extern __shared__ __align__(16) float dsm[];
    float* rawA = dsm;                          // [2][BM][GBKP]
    float* rawB = rawA + G_RAWA;                // [2][BK][GBNP]
    uint32_t* hA = (uint32_t*)(rawB + G_RAWB);  // [BM][GPS]
    uint32_t* lA = hA + G_PA;
    uint32_t* hB = lA + G_PA;                   // [BN][GPS] (n-major)
    uint32_t* lB = hB + G_PB;

    const int tid  = threadIdx.x;
    const int lane = tid & 31;
    const int warp = tid >> 5;
    const int wm = warp & 3;            // 4 warps along M (32 rows each)
    const int wn = warp >> 2;           // 2 along N (64 cols each)
    constexpr int MT  = 2;
    constexpr int NT2 = 8;

    const int qr = lane >> 2;
    const int qc = lane & 3;

    float acc[MT][NT2][4];
#pragma unroll
    for (int mt = 0; mt < MT; mt++)
#pragma unroll
        for (int nt = 0; nt < NT2; nt++)
#pragma unroll
            for (int r = 0; r < 4; r++) acc[mt][nt][r] = 0.0f;

    auto loadA = [&](int kt, int s) {
#pragma unroll
        for (int i = 0; i < 2; i++) {
            int ch  = tid + i * 256;
            int row = ch / (BK / 4);
            int kq  = (ch % (BK / 4)) * 4;
            const float* src = A + (size_t)(m0 + row) * lda + kt * BK + kq;
            uint32_t dst = (uint32_t)__cvta_generic_to_shared(
                &rawA[s * BM * GBKP + row * GBKP + kq]);
            asm volatile("cp.async.cg.shared.global [%0], [%1], 16;" :: "r"(dst), "l"(src));
        }
    };
    auto loadB = [&](int kt, int s) {
#pragma unroll
        for (int i = 0; i < 2; i++) {
            int ch  = tid + i * 256;
            int row = ch / (BN / 4);
            int cq  = (ch % (BN / 4)) * 4;
            const float* src = Bm + (size_t)(kt * BK + row) * ldb + n0 + cq;
            uint32_t dst = (uint32_t)__cvta_generic_to_shared(
                &rawB[s * BK * GBNP + row * GBNP + cq]);
            asm volatile("cp.async.cg.shared.global [%0], [%1], 16;" :: "r"(dst), "l"(src));
        }
    };

    loadA(0, 0); loadB(0, 0);
    asm volatile("cp.async.commit_group;");

    for (int kt = 0; kt < nk; kt++) {
        const int s = kt & 1;
        if (kt + 1 < nk) {
            loadA(kt + 1, s ^ 1); loadB(kt + 1, s ^ 1);
            asm volatile("cp.async.commit_group;");
            asm volatile("cp.async.wait_group 1;");
        } else {
            asm volatile("cp.async.wait_group 0;");
        }
        __syncthreads();   // raw(kt) ready; packed buffers free

        // Split pass A: fp32 -> packed bf16 hi/lo (pairs along k)
#pragma unroll
        for (int i = 0; i < 4; i++) {          // BM*GBKH/256 = 4
            int o   = tid + i * 256;
            int row = o >> 3;
            int kh  = o & 7;
            float2 v = *(float2*)&rawA[s * BM * GBKP + row * GBKP + 2 * kh];
            uint32_t hi, lo;
            split_pack_bf16(v.x, v.y, hi, lo);
            hA[row * GPS + kh] = hi;
            lA[row * GPS + kh] = lo;
        }
        // Split pass B: fp32 [k][n] -> packed bf16 [n][k/2]
#pragma unroll
        for (int i = 0; i < 4; i++) {          // BN*GBKH/256 = 4
            int o  = tid + i * 256;
            int n  = o >> 3;
            int kh = o & 7;
            float x0 = rawB[s * BK * GBNP + (2 * kh    ) * GBNP + n];
            float x1 = rawB[s * BK * GBNP + (2 * kh + 1) * GBNP + n];
            uint32_t hi, lo;
            split_pack_bf16(x0, x1, hi, lo);
            hB[n * GPS + kh] = hi;
            lB[n * GPS + kh] = lo;
        }
        __syncthreads();   // packed ready

        // Pure LDS + bf16 MMA (one k16 step per tile-k)
        uint32_t ahi[MT][4], alo[MT][4];
#pragma unroll
        for (int mt = 0; mt < MT; mt++) {
            int m = wm * 32 + mt * 16 + qr;
            ahi[mt][0] = hA[(m    ) * GPS + qc];
            ahi[mt][1] = hA[(m + 8) * GPS + qc];
            ahi[mt][2] = hA[(m    ) * GPS + qc + 4];
            ahi[mt][3] = hA[(m + 8) * GPS + qc + 4];
            alo[mt][0] = lA[(m    ) * GPS + qc];
            alo[mt][1] = lA[(m + 8) * GPS + qc];
            alo[mt][2] = lA[(m    ) * GPS + qc + 4];
            alo[mt][3] = lA[(m + 8) * GPS + qc + 4];
        }
#pragma unroll
        for (int nt = 0; nt < NT2; nt++) {
            int n = wn * 64 + nt * 8 + qr;
            uint32_t bhi[2], blo[2];
            bhi[0] = hB[n * GPS + qc];
            bhi[1] = hB[n * GPS + qc + 4];
            blo[0] = lB[n * GPS + qc];
            blo[1] = lB[n * GPS + qc + 4];
#pragma unroll
            for (int mt = 0; mt < MT; mt++) {
                mma_bf16(acc[mt][nt], ahi[mt], blo);
                mma_bf16(acc[mt][nt], alo[mt], bhi);
                mma_bf16(acc[mt][nt], ahi[mt], bhi);
            }
        }
    }

#pragma unroll
    for (int mt = 0; mt < MT; mt++)
#pragma unroll
        for (int nt = 0; nt < NT2; nt++) {
            int m = m0 + wm * 32 + mt * 16 + qr;
            int n = n0 + wn * 64 + nt * 8 + 2 * qc;
            size_t o0 = (size_t)m * ldc + n;
            size_t o1 = (size_t)(m + 8) * ldc + n;
            float2 v0 = make_float2(acc[mt][nt][0], acc[mt][nt][1]);
            float2 v1 = make_float2(acc[mt][nt][2], acc[mt][nt][3]);
            if (MODE == 1) {
                v0.x += R[o0]; v0.y += R[o0 + 1];
                v1.x += R[o1]; v1.y += R[o1 + 1];
            }
            *(float2*)(C + o0) = v0;
            *(float2*)(C + o1) = v1;
        }
}

// ---------------- Fused flash attention (tf32x3, online softmax) ------------
__global__ void __launch_bounds__(128)
flash_kernel(const float* __restrict__ Qm, const float* __restrict__ Km,
             const float* __restrict__ Vm, float* __restrict__ Om) {
    extern __shared__ __align__(16) float fsm[];
    float* Ks = fsm;
    float* Vs = fsm + 64 * FSTR;
    float* QP = fsm + 2 * 64 * FSTR;

    const int z = blockIdx.y;
    const int b = z / H_, h = z % H_, kvh = h / NREP_;
    const int q0 = ((int)gridDim.x - 1 - (int)blockIdx.x) * BMF;

    const int tid  = threadIdx.x;
    const int lane = tid & 31;
    const int warp = tid >> 5;
    const int qr = lane >> 2, qc = lane & 3;
    const int wrow = warp * 16;

    const float* Qb = Qm + ((size_t)(b * S_ + q0)) * D_ + h * HD_;
    const float* Kb = Km + ((size_t)b * S_) * (KVH_ * HD_) + kvh * HD_;
    const float* Vb = Vm + ((size_t)b * S_) * (KVH_ * HD_) + kvh * HD_;

    for (int i = tid; i < 64 * 16; i += 128) {
        int r = i >> 4, cq = (i & 15) << 2;
        *(float4*)&QP[r * FSTR + cq] = *(const float4*)(Qb + (size_t)r * D_ + cq);
    }
    __syncthreads();

    uint32_t qhi[8][4], qlo[8][4];
#pragma unroll
    for (int ks = 0; ks < 8; ks++) {
        float a0 = QP[(wrow + qr    ) * FSTR + ks * 8 + qc    ] * 0.125f;
        float a1 = QP[(wrow + qr + 8) * FSTR + ks * 8 + qc    ] * 0.125f;
        float a2 = QP[(wrow + qr    ) * FSTR + ks * 8 + qc + 4] * 0.125f;
        float a3 = QP[(wrow + qr + 8) * FSTR + ks * 8 + qc + 4] * 0.125f;
        split_tf32(a0, qhi[ks][0], qlo[ks][0]);
        split_tf32(a1, qhi[ks][1], qlo[ks][1]);
        split_tf32(a2, qhi[ks][2], qlo[ks][2]);
        split_tf32(a3, qhi[ks][3], qlo[ks][3]);
    }

    float m0 = -INFINITY, m1 = -INFINITY, l0 = 0.f, l1 = 0.f;
    float oa[8][4];
#pragma unroll
    for (int nt = 0; nt < 8; nt++)
#pragma unroll
        for (int r = 0; r < 4; r++) oa[nt][r] = 0.f;

    const int niter = q0 / BNF + 1;
    for (int it = 0; it < niter; it++) {
        const int j0 = it * BNF;
        const bool diag = (j0 == q0);

        __syncthreads();
        for (int i = tid; i < 64 * 16; i += 128) {
            int r = i >> 4, cq = (i & 15) << 2;
            *(float4*)&Ks[r * FSTR + cq] =
                *(const float4*)(Kb + (size_t)(j0 + r) * (KVH_ * HD_) + cq);
            *(float4*)&Vs[r * FSTR + cq] =
                *(const float4*)(Vb + (size_t)(j0 + r) * (KVH_ * HD_) + cq);
        }
        __syncthreads();

        float sa[8][4];
#pragma unroll
        for (int nt = 0; nt < 8; nt++)
#pragma unroll
            for (int r = 0; r < 4; r++) sa[nt][r] = 0.f;

#pragma unroll
        for (int ks = 0; ks < 8; ks++) {
            uint32_t bhi[8][2], blo[8][2];
#pragma unroll
            for (int nt = 0; nt < 8; nt++) {
                float b0 = Ks[(nt * 8 + qr) * FSTR + ks * 8 + qc    ];
                float b1 = Ks[(nt * 8 + qr) * FSTR + ks * 8 + qc + 4];
                split_tf32(b0, bhi[nt][0], blo[nt][0]);
                split_tf32(b1, bhi[nt][1], blo[nt][1]);
            }
#pragma unroll
            for (int nt = 0; nt < 8; nt++) {
                mma_tf32(sa[nt], qhi[ks], blo[nt]);
                mma_tf32(sa[nt], qlo[ks], bhi[nt]);
                mma_tf32(sa[nt], qhi[ks], bhi[nt]);
            }
        }

        if (diag) {
#pragma unroll
            for (int nt = 0; nt < 8; nt++)
#pragma unroll
                for (int r = 0; r < 4; r++) {
                    int row = wrow + qr + ((r >> 1) << 3);
                    int col = nt * 8 + 2 * qc + (r & 1);
                    if (col > row) sa[nt][r] = -INFINITY;
                }
        }

        float mx0 = -INFINITY, mx1 = -INFINITY;
#pragma unroll
        for (int nt = 0; nt < 8; nt++) {
            mx0 = fmaxf(mx0, fmaxf(sa[nt][0], sa[nt][1]));
            mx1 = fmaxf(mx1, fmaxf(sa[nt][2], sa[nt][3]));
        }
        mx0 = fmaxf(mx0, __shfl_xor_sync(0xffffffffu, mx0, 1));
        mx0 = fmaxf(mx0, __shfl_xor_sync(0xffffffffu, mx0, 2));
        mx1 = fmaxf(mx1, __shfl_xor_sync(0xffffffffu, mx1, 1));
        mx1 = fmaxf(mx1, __shfl_xor_sync(0xffffffffu, mx1, 2));

        float mn0 = fmaxf(m0, mx0), mn1 = fmaxf(m1, mx1);
        float c0 = __expf(m0 - mn0), c1 = __expf(m1 - mn1);

        float rs0 = 0.f, rs1 = 0.f;
#pragma unroll
        for (int nt = 0; nt < 8; nt++) {
            float p0 = __expf(sa[nt][0] - mn0);
            float p1 = __expf(sa[nt][1] - mn0);
            float p2 = __expf(sa[nt][2] - mn1);
            float p3 = __expf(sa[nt][3] - mn1);
            rs0 += p0 + p1; rs1 += p2 + p3;
            QP[(wrow + qr    ) * FSTR + nt * 8 + 2 * qc    ] = p0;
            QP[(wrow + qr    ) * FSTR + nt * 8 + 2 * qc + 1] = p1;
            QP[(wrow + qr + 8) * FSTR + nt * 8 + 2 * qc    ] = p2;
            QP[(wrow + qr + 8) * FSTR + nt * 8 + 2 * qc + 1] = p3;
        }
        rs0 += __shfl_xor_sync(0xffffffffu, rs0, 1);
        rs0 += __shfl_xor_sync(0xffffffffu, rs0, 2);
        rs1 += __shfl_xor_sync(0xffffffffu, rs1, 1);
        rs1 += __shfl_xor_sync(0xffffffffu, rs1, 2);

        l0 = l0 * c0 + rs0; l1 = l1 * c1 + rs1;
        m0 = mn0; m1 = mn1;
#pragma unroll
        for (int nt = 0; nt < 8; nt++) {
            oa[nt][0] *= c0; oa[nt][1] *= c0;
            oa[nt][2] *= c1; oa[nt][3] *= c1;
        }

        __syncwarp();

#pragma unroll
        for (int ks = 0; ks < 8; ks++) {
            float a0 = QP[(wrow + qr    ) * FSTR + ks * 8 + qc    ];
            float a1 = QP[(wrow + qr + 8) * FSTR + ks * 8 + qc    ];
            float a2 = QP[(wrow + qr    ) * FSTR + ks * 8 + qc + 4];
            float a3 = QP[(wrow + qr + 8) * FSTR + ks * 8 + qc + 4];
            uint32_t phi[4], plo[4];
            split_tf32(a0, phi[0], plo[0]);
            split_tf32(a1, phi[1], plo[1]);
            split_tf32(a2, phi[2], plo[2]);
            split_tf32(a3, phi[3], plo[3]);
#pragma unroll
            for (int nt = 0; nt < 8; nt++) {
                uint32_t vhi[2], vlo[2];
                float b0 = Vs[(ks * 8 + qc    ) * FSTR + nt * 8 + qr];
                float b1 = Vs[(ks * 8 + qc + 4) * FSTR + nt * 8 + qr];
                split_tf32(b0, vhi[0], vlo[0]);
                split_tf32(b1, vhi[1], vlo[1]);
                mma_tf32(oa[nt], phi, vlo);
                mma_tf32(oa[nt], plo, vhi);
                mma_tf32(oa[nt], phi, vhi);
            }
        }
    }

    float inv0 = 1.f / l0, inv1 = 1.f / l1;
    float* Ob = Om + ((size_t)(b * S_ + q0)) * D_ + h * HD_;
#pragma unroll
    for (int nt = 0; nt < 8; nt++) {
        int col = nt * 8 + 2 * qc;
        *(float2*)(Ob + (size_t)(wrow + qr) * D_ + col) =
            make_float2(oa[nt][0] * inv0, oa[nt][1] * inv0);
        *(float2*)(Ob + (size_t)(wrow + qr + 8) * D_ + col) =
            make_float2(oa[nt][2] * inv1, oa[nt][3] * inv1);
    }
}

// ---------------- SwiGLU: f0 = silu(f0) * f1 -------------------------------
__global__ void silu_mul_kernel() {
    int idx = blockIdx.x * blockDim.x + threadIdx.x;
    if (idx >= T_ * FF_) return;
    float a = g_f0[idx];
    float b = g_f1[idx];
    g_f0[idx] = a / (1.0f + expf(-a)) * b;
}

// ---------------- Launch ----------------------------------------------------
extern "C" void kernel_launch(void* const* d_in, const int* in_sizes, int n_in,
                              void* d_out, int out_size) {
    const float* x  = (const float*)d_in[0];
    const float* Wq = (const float*)d_in[1];
    const float* Wk = (const float*)d_in[2];
    const float* Wv = (const float*)d_in[3];
    const float* Wo = (const float*)d_in[4];
    const float* an = (const float*)d_in[5];
    const float* w0 = (const float*)d_in[6];
    const float* w1 = (const float*)d_in[7];
    const float* w2 = (const float*)d_in[8];
    const float* sn = (const float*)d_in[9];
    const float* on = (const float*)d_in[10];
    float* out = (float*)d_out;

    float *px, *ph, *pq, *pk, *pvv, *pattn, *pf0, *pf1;
    cudaGetSymbolAddress((void**)&px,    g_x);
    cudaGetSymbolAddress((void**)&ph,    g_h);
    cudaGetSymbolAddress((void**)&pq,    g_q);
    cudaGetSymbolAddress((void**)&pk,    g_kbuf);
    cudaGetSymbolAddress((void**)&pvv,   g_vbuf);
    cudaGetSymbolAddress((void**)&pattn, g_attn);
    cudaGetSymbolAddress((void**)&pf0,   g_f0);
    cudaGetSymbolAddress((void**)&pf1,   g_f1);

    cudaFuncSetAttribute(flash_kernel,
                         cudaFuncAttributeMaxDynamicSharedMemorySize, FSMEM_BYTES);
    cudaFuncSetAttribute(mma_gemm<0>,
                         cudaFuncAttributeMaxDynamicSharedMemorySize, GSMEM_BYTES);
    cudaFuncSetAttribute(mma_gemm<1>,
                         cudaFuncAttributeMaxDynamicSharedMemorySize, GSMEM_BYTES);
    cudaFuncSetAttribute(mma_gemm<5>,
                         cudaFuncAttributeMaxDynamicSharedMemorySize, GSMEM_BYTES);

    rope_table_kernel<<<(S_*HALF_HD_ + 255)/256, 256>>>();

    for (int i = 0; i < L_; i++) {
        const float* xin = (i == 0) ? x : px;

        rmsnorm_kernel<<<T_, 256>>>(xin, an + (size_t)i * D_, ph);

        // fused QKV projection: one launch, grid (6+2+2, 32)
        mma_gemm<5><<<dim3(10, T_/128), 256, GSMEM_BYTES>>>(
            ph, Wq + (size_t)i*D_*D_, nullptr, pq, D_, D_, D_, D_,
            Wk + (size_t)i*D_*(KVH_*HD_), Wv + (size_t)i*D_*(KVH_*HD_), pk, pvv);

        {
            int tq = T_ * H_ * HALF_HD_;
            rope_kernel<<<(tq + 255)/256, 256>>>(pq, H_, tq);
            int tk = T_ * KVH_ * HALF_HD_;
            rope_kernel<<<(tk + 255)/256, 256>>>(pk, KVH_, tk);
        }

        flash_kernel<<<dim3(S_/BMF, B_*H_), 128, FSMEM_BYTES>>>(pq, pk, pvv, pattn);

        mma_gemm<1><<<dim3(D_/128, T_/128), 256, GSMEM_BYTES>>>(
            pattn, Wo + (size_t)i*D_*D_, xin, px, D_, D_, D_, D_,
            nullptr, nullptr, nullptr, nullptr);

        rmsnorm_kernel<<<T_, 256>>>(px, sn + (size_t)i * D_, ph);

        mma_gemm<0><<<dim3(FF_/128, T_/128), 256, GSMEM_BYTES>>>(
            ph, w0 + (size_t)i*D_*FF_, nullptr, pf0, D_, D_, FF_, FF_,
            nullptr, nullptr, nullptr, nullptr);
        mma_gemm<0><<<dim3(FF_/128, T_/128), 256, GSMEM_BYTES>>>(
            ph, w1 + (size_t)i*D_*FF_, nullptr, pf1, D_, D_, FF_, FF_,
            nullptr, nullptr, nullptr, nullptr);
        silu_mul_kernel<<<(T_*FF_ + 255)/256, 256>>>();
        mma_gemm<1><<<dim3(D_/128, T_/128), 256, GSMEM_BYTES>>>(
            pf0, w2 + (size_t)i*FF_*D_, px, px, FF_, FF_, D_, D_,
            nullptr, nullptr, nullptr, nullptr);
    }

    rmsnorm_kernel<<<T_, 256>>>(px, on, out);
}

// round 13
// speedup vs baseline: 2.1885x; 1.0669x over previous
#include <cuda_runtime.h>
#include <cuda_bf16.h>
#include <math.h>
#include <stdint.h>

// Problem constants
#define L_    2
#define B_    2
#define S_    2048
#define D_    768
#define H_    12
#define KVH_  4
#define HD_   64
#define NREP_ 3
#define FF_   3072
#define T_    (B_*S_)          // 4096 tokens
#define HALF_HD_ 32

// Flash tile config (bf16x3)
#define BMF 64
#define BNF 64
#define FKP 36                              // packed row stride (uint32)
#define F2_RAW (64*68)                      // floats per raw tile
#define F2_PK  (64*FKP)                     // uint32 per packed array
#define FSMEM_BYTES (2*F2_RAW*4 + 4*F2_PK*4)  // 34816 + 36864 = 71680 B

// GEMM smem config (dynamic)
#define GBM 128
#define GBN 128
#define GBK 16
#define GPS 12             // packed row stride in uint32
#define GBKP (GBK + 4)     // 20
#define GBNP (GBN + 4)     // 132
#define G_RAWA (2 * GBM * GBKP)            // floats
#define G_RAWB (2 * GBK * GBNP)
#define G_PA   (GBM * GPS)                 // uint32
#define G_PB   (GBN * GPS)
#define GSMEM_BYTES ((G_RAWA + G_RAWB) * 4 + 4 * G_PA * 4)   // 61952 B

// ---------------- Scratch (device globals; no allocation allowed) ----------
__device__ float g_x[T_*D_];
__device__ float g_h[T_*D_];
__device__ float g_q[T_*D_];
__device__ float g_kbuf[T_*KVH_*HD_];
__device__ float g_vbuf[T_*KVH_*HD_];
__device__ float g_attn[T_*D_];
__device__ float g_f0[T_*FF_];
__device__ float g_f1[T_*FF_];
__device__ float g_ct[S_*HALF_HD_];
__device__ float g_st[S_*HALF_HD_];

// ---------------- RoPE tables ----------------------------------------------
__global__ void rope_table_kernel() {
    int idx = blockIdx.x * blockDim.x + threadIdx.x;
    if (idx >= S_ * HALF_HD_) return;
    int s = idx / HALF_HD_;
    int i = idx % HALF_HD_;
    double freq = exp(-log(10000.0) * (double)(2 * i) / (double)HD_);
    float ff = (float)freq;
    float ang = (float)s * ff;
    g_ct[idx] = (float)cos((double)ang);
    g_st[idx] = (float)sin((double)ang);
}

// ---------------- RMSNorm ---------------------------------------------------
__global__ void rmsnorm_kernel(const float* __restrict__ in,
                               const float* __restrict__ w,
                               float* __restrict__ out) {
    int row = blockIdx.x;
    int tid = threadIdx.x;
    const float* p = in + (size_t)row * D_;
    float v0 = p[tid], v1 = p[tid + 256], v2 = p[tid + 512];
    float ss = v0 * v0 + v1 * v1 + v2 * v2;
    __shared__ float red[256];
    red[tid] = ss;
    __syncthreads();
    for (int o = 128; o > 0; o >>= 1) {
        if (tid < o) red[tid] += red[tid + o];
        __syncthreads();
    }
    float inv = rsqrtf(red[0] * (1.0f / (float)D_) + 1e-6f);
    float* q = out + (size_t)row * D_;
    q[tid]       = v0 * inv * w[tid];
    q[tid + 256] = v1 * inv * w[tid + 256];
    q[tid + 512] = v2 * inv * w[tid + 512];
}

// ---------------- numeric helpers -------------------------------------------
__device__ __forceinline__ void mma_bf16(float* c, const uint32_t* a, const uint32_t* b) {
    asm volatile(
        "mma.sync.aligned.m16n8k16.row.col.f32.bf16.bf16.f32 "
        "{%0,%1,%2,%3}, {%4,%5,%6,%7}, {%8,%9}, {%0,%1,%2,%3};"
        : "+f"(c[0]), "+f"(c[1]), "+f"(c[2]), "+f"(c[3])
        : "r"(a[0]), "r"(a[1]), "r"(a[2]), "r"(a[3]), "r"(b[0]), "r"(b[1]));
}

// Split two fp32 into bf16 hi/lo, packed along k (x0 -> low half).
__device__ __forceinline__ void split_pack_bf16(float x0, float x1,
                                                uint32_t& hi, uint32_t& lo) {
    __nv_bfloat16 h0 = __float2bfloat16_rn(x0);
    __nv_bfloat16 h1 = __float2bfloat16_rn(x1);
    __nv_bfloat16 l0 = __float2bfloat16_rn(x0 - __bfloat162float(h0));
    __nv_bfloat16 l1 = __float2bfloat16_rn(x1 - __bfloat162float(h1));
    hi = (uint32_t)__bfloat16_as_ushort(h0) | ((uint32_t)__bfloat16_as_ushort(h1) << 16);
    lo = (uint32_t)__bfloat16_as_ushort(l0) | ((uint32_t)__bfloat16_as_ushort(l1) << 16);
}

// ---------------- Tensor-core GEMM (bf16 x3 split, m16n8k16) ----------------
// MODE 0: C = A @ B
// MODE 1: C = A @ B + R
// MODE 5: fused QKV + RoPE — n-blocks 0..5 -> Q, 6..7 -> K (rope applied), 8..9 -> V
// MODE 6: C = silu(R) * (A @ B)
template<int MODE>
__global__ void __launch_bounds__(256, 2)
mma_gemm(const float* __restrict__ A, const float* __restrict__ Bm,
         const float* __restrict__ R, float* __restrict__ C,
         int K, int lda, int ldb, int ldc,
         const float* __restrict__ B2, const float* __restrict__ B3,
         float* __restrict__ C2, float* __restrict__ C3)
{
    constexpr int BM = GBM, BN = GBN, BK = GBK;
    const int m0 = blockIdx.y * BM;
    int n0 = blockIdx.x * BN;

    if (MODE == 5) {
        int nb = blockIdx.x;
        if (nb >= 6) {
            if (nb >= 8) { Bm = B3; C = C3; nb -= 8; }
            else         { Bm = B2; C = C2; nb -= 6; }
            ldb = KVH_ * HD_; ldc = KVH_ * HD_;
        }
        n0 = nb * BN;
    }
    const int nk = K / BK;

    extern __shared__ __align__(16) float dsm[];
    float* rawA = dsm;                          // [2][BM][GBKP]
    float* rawB = rawA + G_RAWA;                // [2][BK][GBNP]
    uint32_t* hA = (uint32_t*)(rawB + G_RAWB);  // [BM][GPS]
    uint32_t* lA = hA + G_PA;
    uint32_t* hB = lA + G_PA;                   // [BN][GPS]
    uint32_t* lB = hB + G_PB;

    const int tid  = threadIdx.x;
    const int lane = tid & 31;
    const int warp = tid >> 5;
    const int wm = warp & 3;
    const int wn = warp >> 2;
    constexpr int MT  = 2;
    constexpr int NT2 = 8;

    const int qr = lane >> 2;
    const int qc = lane & 3;

    float acc[MT][NT2][4];
#pragma unroll
    for (int mt = 0; mt < MT; mt++)
#pragma unroll
        for (int nt = 0; nt < NT2; nt++)
#pragma unroll
            for (int r = 0; r < 4; r++) acc[mt][nt][r] = 0.0f;

    auto loadA = [&](int kt, int s) {
#pragma unroll
        for (int i = 0; i < 2; i++) {
            int ch  = tid + i * 256;
            int row = ch / (BK / 4);
            int kq  = (ch % (BK / 4)) * 4;
            const float* src = A + (size_t)(m0 + row) * lda + kt * BK + kq;
            uint32_t dst = (uint32_t)__cvta_generic_to_shared(
                &rawA[s * BM * GBKP + row * GBKP + kq]);
            asm volatile("cp.async.cg.shared.global [%0], [%1], 16;" :: "r"(dst), "l"(src));
        }
    };
    auto loadB = [&](int kt, int s) {
#pragma unroll
        for (int i = 0; i < 2; i++) {
            int ch  = tid + i * 256;
            int row = ch / (BN / 4);
            int cq  = (ch % (BN / 4)) * 4;
            const float* src = Bm + (size_t)(kt * BK + row) * ldb + n0 + cq;
            uint32_t dst = (uint32_t)__cvta_generic_to_shared(
                &rawB[s * BK * GBNP + row * GBNP + cq]);
            asm volatile("cp.async.cg.shared.global [%0], [%1], 16;" :: "r"(dst), "l"(src));
        }
    };

    loadA(0, 0); loadB(0, 0);
    asm volatile("cp.async.commit_group;");

    for (int kt = 0; kt < nk; kt++) {
        const int s = kt & 1;
        if (kt + 1 < nk) {
            loadA(kt + 1, s ^ 1); loadB(kt + 1, s ^ 1);
            asm volatile("cp.async.commit_group;");
            asm volatile("cp.async.wait_group 1;");
        } else {
            asm volatile("cp.async.wait_group 0;");
        }
        __syncthreads();

#pragma unroll
        for (int i = 0; i < 4; i++) {
            int o   = tid + i * 256;
            int row = o >> 3;
            int kh  = o & 7;
            float2 v = *(float2*)&rawA[s * BM * GBKP + row * GBKP + 2 * kh];
            uint32_t hi, lo;
            split_pack_bf16(v.x, v.y, hi, lo);
            hA[row * GPS + kh] = hi;
            lA[row * GPS + kh] = lo;
        }
#pragma unroll
        for (int i = 0; i < 4; i++) {
            int o  = tid + i * 256;
            int n  = o >> 3;
            int kh = o & 7;
            float x0 = rawB[s * BK * GBNP + (2 * kh    ) * GBNP + n];
            float x1 = rawB[s * BK * GBNP + (2 * kh + 1) * GBNP + n];
            uint32_t hi, lo;
            split_pack_bf16(x0, x1, hi, lo);
            hB[n * GPS + kh] = hi;
            lB[n * GPS + kh] = lo;
        }
        __syncthreads();

        uint32_t ahi[MT][4], alo[MT][4];
#pragma unroll
        for (int mt = 0; mt < MT; mt++) {
            int m = wm * 32 + mt * 16 + qr;
            ahi[mt][0] = hA[(m    ) * GPS + qc];
            ahi[mt][1] = hA[(m + 8) * GPS + qc];
            ahi[mt][2] = hA[(m    ) * GPS + qc + 4];
            ahi[mt][3] = hA[(m + 8) * GPS + qc + 4];
            alo[mt][0] = lA[(m    ) * GPS + qc];
            alo[mt][1] = lA[(m + 8) * GPS + qc];
            alo[mt][2] = lA[(m    ) * GPS + qc + 4];
            alo[mt][3] = lA[(m + 8) * GPS + qc + 4];
        }
#pragma unroll
        for (int nt = 0; nt < NT2; nt++) {
            int n = wn * 64 + nt * 8 + qr;
            uint32_t bhi[2], blo[2];
            bhi[0] = hB[n * GPS + qc];
            bhi[1] = hB[n * GPS + qc + 4];
            blo[0] = lB[n * GPS + qc];
            blo[1] = lB[n * GPS + qc + 4];
#pragma unroll
            for (int mt = 0; mt < MT; mt++) {
                mma_bf16(acc[mt][nt], ahi[mt], blo);
                mma_bf16(acc[mt][nt], alo[mt], bhi);
                mma_bf16(acc[mt][nt], ahi[mt], bhi);
            }
        }
    }

#pragma unroll
    for (int mt = 0; mt < MT; mt++)
#pragma unroll
        for (int nt = 0; nt < NT2; nt++) {
            int m = m0 + wm * 32 + mt * 16 + qr;
            int n = n0 + wn * 64 + nt * 8 + 2 * qc;
            size_t o0 = (size_t)m * ldc + n;
            size_t o1 = (size_t)(m + 8) * ldc + n;
            float2 v0 = make_float2(acc[mt][nt][0], acc[mt][nt][1]);
            float2 v1 = make_float2(acc[mt][nt][2], acc[mt][nt][3]);
            if (MODE == 1) {
                v0.x += R[o0]; v0.y += R[o0 + 1];
                v1.x += R[o1]; v1.y += R[o1 + 1];
            }
            if (MODE == 6) {
                float r0 = R[o0], r1 = R[o0 + 1], r2 = R[o1], r3 = R[o1 + 1];
                v0.x *= r0 / (1.0f + expf(-r0));
                v0.y *= r1 / (1.0f + expf(-r1));
                v1.x *= r2 / (1.0f + expf(-r2));
                v1.y *= r3 / (1.0f + expf(-r3));
            }
            if (MODE == 5 && blockIdx.x < 8) {
                // RoPE on Q/K outputs (n even => pair (n, n+1) within head dim)
                int i0 = (n & (HD_ - 1)) >> 1;
                {
                    int srow = m % S_;
                    float c = g_ct[srow * HALF_HD_ + i0];
                    float sn = g_st[srow * HALF_HD_ + i0];
                    float r0 = v0.x * c - v0.y * sn;
                    float r1 = v0.x * sn + v0.y * c;
                    v0.x = r0; v0.y = r1;
                }
                {
                    int srow = (m + 8) % S_;
                    float c = g_ct[srow * HALF_HD_ + i0];
                    float sn = g_st[srow * HALF_HD_ + i0];
                    float r0 = v1.x * c - v1.y * sn;
                    float r1 = v1.x * sn + v1.y * c;
                    v1.x = r0; v1.y = r1;
                }
            }
            *(float2*)(C + o0) = v0;
            *(float2*)(C + o1) = v1;
        }
}

// ---------------- Fused flash attention (bf16x3, online softmax) ------------
// One CTA = 64 Q rows of one (b,h). 128 threads, 4 warps * 16 rows.
__global__ void __launch_bounds__(128)
flash_kernel(const float* __restrict__ Qm, const float* __restrict__ Km,
             const float* __restrict__ Vm, float* __restrict__ Om) {
    extern __shared__ __align__(16) float fsm[];
    float* rawK = fsm;                       // [64][68] (Q staging first)
    float* rawV = fsm + F2_RAW;              // [64][68]
    uint32_t* pKh = (uint32_t*)(fsm + 2 * F2_RAW);
    uint32_t* pKl = pKh + F2_PK;
    uint32_t* pVh = pKl + F2_PK;
    uint32_t* pVl = pVh + F2_PK;

    const int z = blockIdx.y;
    const int b = z / H_, h = z % H_, kvh = h / NREP_;
    const int q0 = ((int)gridDim.x - 1 - (int)blockIdx.x) * BMF;

    const int tid  = threadIdx.x;
    const int lane = tid & 31;
    const int warp = tid >> 5;
    const int qr = lane >> 2, qc = lane & 3;
    const int wrow = warp * 16;

    const float* Qb = Qm + ((size_t)(b * S_ + q0)) * D_ + h * HD_;
    const float* Kb = Km + ((size_t)b * S_) * (KVH_ * HD_) + kvh * HD_;
    const float* Vb = Vm + ((size_t)b * S_) * (KVH_ * HD_) + kvh * HD_;

    // stage Q in rawK
    for (int i = tid; i < 64 * 16; i += 128) {
        int r = i >> 4, cq = (i & 15) << 2;
        *(float4*)&rawK[r * 68 + cq] = *(const float4*)(Qb + (size_t)r * D_ + cq);
    }
    __syncthreads();

    // Q fragments, bf16 hi/lo, scaled by 1/sqrt(HD)
    uint32_t qhi[4][4], qlo[4][4];
#pragma unroll
    for (int s = 0; s < 4; s++) {
        int r0 = wrow + qr, r1 = r0 + 8;
        int k0 = 16 * s + 2 * qc, k1 = k0 + 8;
        split_pack_bf16(rawK[r0*68+k0]*0.125f, rawK[r0*68+k0+1]*0.125f, qhi[s][0], qlo[s][0]);
        split_pack_bf16(rawK[r1*68+k0]*0.125f, rawK[r1*68+k0+1]*0.125f, qhi[s][1], qlo[s][1]);
        split_pack_bf16(rawK[r0*68+k1]*0.125f, rawK[r0*68+k1+1]*0.125f, qhi[s][2], qlo[s][2]);
        split_pack_bf16(rawK[r1*68+k1]*0.125f, rawK[r1*68+k1+1]*0.125f, qhi[s][3], qlo[s][3]);
    }

    float m0 = -INFINITY, m1 = -INFINITY, l0 = 0.f, l1 = 0.f;
    float oa[8][4];
#pragma unroll
    for (int nt = 0; nt < 8; nt++)
#pragma unroll
        for (int r = 0; r < 4; r++) oa[nt][r] = 0.f;

    const int niter = q0 / BNF + 1;
    for (int it = 0; it < niter; it++) {
        const int j0 = it * BNF;
        const bool diag = (j0 == q0);

        __syncthreads();   // prior packed-consumers (and Q-frag reads) done
        for (int i = tid; i < 64 * 16; i += 128) {
            int r = i >> 4, cq2 = (i & 15) << 2;
            *(float4*)&rawK[r * 68 + cq2] =
                *(const float4*)(Kb + (size_t)(j0 + r) * (KVH_ * HD_) + cq2);
            *(float4*)&rawV[r * 68 + cq2] =
                *(const float4*)(Vb + (size_t)(j0 + r) * (KVH_ * HD_) + cq2);
        }
        __syncthreads();

        // pack K: entry (n=seq, kp=hd-pair)
#pragma unroll
        for (int i = 0; i < 16; i++) {
            int o = tid + i * 128;
            int n = o >> 5, kp = o & 31;
            float2 v = *(float2*)&rawK[n * 68 + 2 * kp];
            uint32_t hi, lo;
            split_pack_bf16(v.x, v.y, hi, lo);
            pKh[n * FKP + kp] = hi;
            pKl[n * FKP + kp] = lo;
        }
        // pack V: entry (n=hd, kp=seq-pair)
#pragma unroll
        for (int i = 0; i < 16; i++) {
            int o = tid + i * 128;
            int kp = o >> 6, n = o & 63;
            float x0 = rawV[(2 * kp)     * 68 + n];
            float x1 = rawV[(2 * kp + 1) * 68 + n];
            uint32_t hi, lo;
            split_pack_bf16(x0, x1, hi, lo);
            pVh[n * FKP + kp] = hi;
            pVl[n * FKP + kp] = lo;
        }
        __syncthreads();

        // S = Q @ K^T
        float sa[8][4];
#pragma unroll
        for (int nt = 0; nt < 8; nt++)
#pragma unroll
            for (int r = 0; r < 4; r++) sa[nt][r] = 0.f;

#pragma unroll
        for (int s = 0; s < 4; s++) {
#pragma unroll
            for (int nt = 0; nt < 8; nt++) {
                int n = nt * 8 + qr;
                uint32_t bh[2], bl[2];
                bh[0] = pKh[n * FKP + 8 * s + qc];
                bh[1] = pKh[n * FKP + 8 * s + qc + 4];
                bl[0] = pKl[n * FKP + 8 * s + qc];
                bl[1] = pKl[n * FKP + 8 * s + qc + 4];
                mma_bf16(sa[nt], qhi[s], bl);
                mma_bf16(sa[nt], qlo[s], bh);
                mma_bf16(sa[nt], qhi[s], bh);
            }
        }

        if (diag) {
#pragma unroll
            for (int nt = 0; nt < 8; nt++)
#pragma unroll
                for (int r = 0; r < 4; r++) {
                    int row = wrow + qr + ((r >> 1) << 3);
                    int col = nt * 8 + 2 * qc + (r & 1);
                    if (col > row) sa[nt][r] = -INFINITY;
                }
        }

        // online softmax
        float mx0 = -INFINITY, mx1 = -INFINITY;
#pragma unroll
        for (int nt = 0; nt < 8; nt++) {
            mx0 = fmaxf(mx0, fmaxf(sa[nt][0], sa[nt][1]));
            mx1 = fmaxf(mx1, fmaxf(sa[nt][2], sa[nt][3]));
        }
        mx0 = fmaxf(mx0, __shfl_xor_sync(0xffffffffu, mx0, 1));
        mx0 = fmaxf(mx0, __shfl_xor_sync(0xffffffffu, mx0, 2));
        mx1 = fmaxf(mx1, __shfl_xor_sync(0xffffffffu, mx1, 1));
        mx1 = fmaxf(mx1, __shfl_xor_sync(0xffffffffu, mx1, 2));

        float mn0 = fmaxf(m0, mx0), mn1 = fmaxf(m1, mx1);
        float c0 = __expf(m0 - mn0), c1 = __expf(m1 - mn1);

        float rs0 = 0.f, rs1 = 0.f;
#pragma unroll
        for (int nt = 0; nt < 8; nt++) {
            float p0 = __expf(sa[nt][0] - mn0);
            float p1 = __expf(sa[nt][1] - mn0);
            float p2 = __expf(sa[nt][2] - mn1);
            float p3 = __expf(sa[nt][3] - mn1);
            rs0 += p0 + p1; rs1 += p2 + p3;
            sa[nt][0] = p0; sa[nt][1] = p1; sa[nt][2] = p2; sa[nt][3] = p3;
        }
        rs0 += __shfl_xor_sync(0xffffffffu, rs0, 1);
        rs0 += __shfl_xor_sync(0xffffffffu, rs0, 2);
        rs1 += __shfl_xor_sync(0xffffffffu, rs1, 1);
        rs1 += __shfl_xor_sync(0xffffffffu, rs1, 2);

        l0 = l0 * c0 + rs0; l1 = l1 * c1 + rs1;
        m0 = mn0; m1 = mn1;
#pragma unroll
        for (int nt = 0; nt < 8; nt++) {
            oa[nt][0] *= c0; oa[nt][1] *= c0;
            oa[nt][2] *= c1; oa[nt][3] *= c1;
        }

        // O += P @ V  — P fragments packed in registers from sa
#pragma unroll
        for (int s = 0; s < 4; s++) {
            uint32_t phi[4], plo[4];
            split_pack_bf16(sa[2*s  ][0], sa[2*s  ][1], phi[0], plo[0]);
            split_pack_bf16(sa[2*s  ][2], sa[2*s  ][3], phi[1], plo[1]);
            split_pack_bf16(sa[2*s+1][0], sa[2*s+1][1], phi[2], plo[2]);
            split_pack_bf16(sa[2*s+1][2], sa[2*s+1][3], phi[3], plo[3]);
#pragma unroll
            for (int nt = 0; nt < 8; nt++) {
                int n = nt * 8 + qr;
                uint32_t bh[2], bl[2];
                bh[0] = pVh[n * FKP + 8 * s + qc];
                bh[1] = pVh[n * FKP + 8 * s + qc + 4];
                bl[0] = pVl[n * FKP + 8 * s + qc];
                bl[1] = pVl[n * FKP + 8 * s + qc + 4];
                mma_bf16(oa[nt], phi, bl);
                mma_bf16(oa[nt], plo, bh);
                mma_bf16(oa[nt], phi, bh);
            }
        }
    }

    float inv0 = 1.f / l0, inv1 = 1.f / l1;
    float* Ob = Om + ((size_t)(b * S_ + q0)) * D_ + h * HD_;
#pragma unroll
    for (int nt = 0; nt < 8; nt++) {
        int col = nt * 8 + 2 * qc;
        *(float2*)(Ob + (size_t)(wrow + qr) * D_ + col) =
            make_float2(oa[nt][0] * inv0, oa[nt][1] * inv0);
        *(float2*)(Ob + (size_t)(wrow + qr + 8) * D_ + col) =
            make_float2(oa[nt][2] * inv1, oa[nt][3] * inv1);
    }
}

// ---------------- Launch ----------------------------------------------------
extern "C" void kernel_launch(void* const* d_in, const int* in_sizes, int n_in,
                              void* d_out, int out_size) {
    const float* x  = (const float*)d_in[0];
    const float* Wq = (const float*)d_in[1];
    const float* Wk = (const float*)d_in[2];
    const float* Wv = (const float*)d_in[3];
    const float* Wo = (const float*)d_in[4];
    const float* an = (const float*)d_in[5];
    const float* w0 = (const float*)d_in[6];
    const float* w1 = (const float*)d_in[7];
    const float* w2 = (const float*)d_in[8];
    const float* sn = (const float*)d_in[9];
    const float* on = (const float*)d_in[10];
    float* out = (float*)d_out;

    float *px, *ph, *pq, *pk, *pvv, *pattn, *pf0, *pf1;
    cudaGetSymbolAddress((void**)&px,    g_x);
    cudaGetSymbolAddress((void**)&ph,    g_h);
    cudaGetSymbolAddress((void**)&pq,    g_q);
    cudaGetSymbolAddress((void**)&pk,    g_kbuf);
    cudaGetSymbolAddress((void**)&pvv,   g_vbuf);
    cudaGetSymbolAddress((void**)&pattn, g_attn);
    cudaGetSymbolAddress((void**)&pf0,   g_f0);
    cudaGetSymbolAddress((void**)&pf1,   g_f1);

    cudaFuncSetAttribute(flash_kernel,
                         cudaFuncAttributeMaxDynamicSharedMemorySize, FSMEM_BYTES);
    cudaFuncSetAttribute(mma_gemm<0>,
                         cudaFuncAttributeMaxDynamicSharedMemorySize, GSMEM_BYTES);
    cudaFuncSetAttribute(mma_gemm<1>,
                         cudaFuncAttributeMaxDynamicSharedMemorySize, GSMEM_BYTES);
    cudaFuncSetAttribute(mma_gemm<5>,
                         cudaFuncAttributeMaxDynamicSharedMemorySize, GSMEM_BYTES);
    cudaFuncSetAttribute(mma_gemm<6>,
                         cudaFuncAttributeMaxDynamicSharedMemorySize, GSMEM_BYTES);

    rope_table_kernel<<<(S_*HALF_HD_ + 255)/256, 256>>>();

    for (int i = 0; i < L_; i++) {
        const float* xin = (i == 0) ? x : px;

        rmsnorm_kernel<<<T_, 256>>>(xin, an + (size_t)i * D_, ph);

        // fused QKV projection + RoPE epilogue
        mma_gemm<5><<<dim3(10, T_/128), 256, GSMEM_BYTES>>>(
            ph, Wq + (size_t)i*D_*D_, nullptr, pq, D_, D_, D_, D_,
            Wk + (size_t)i*D_*(KVH_*HD_), Wv + (size_t)i*D_*(KVH_*HD_), pk, pvv);

        flash_kernel<<<dim3(S_/BMF, B_*H_), 128, FSMEM_BYTES>>>(pq, pk, pvv, pattn);

        mma_gemm<1><<<dim3(D_/128, T_/128), 256, GSMEM_BYTES>>>(
            pattn, Wo + (size_t)i*D_*D_, xin, px, D_, D_, D_, D_,
            nullptr, nullptr, nullptr, nullptr);

        rmsnorm_kernel<<<T_, 256>>>(px, sn + (size_t)i * D_, ph);

        mma_gemm<0><<<dim3(FF_/128, T_/128), 256, GSMEM_BYTES>>>(
            ph, w0 + (size_t)i*D_*FF_, nullptr, pf0, D_, D_, FF_, FF_,
            nullptr, nullptr, nullptr, nullptr);
        // w1 with fused SwiGLU epilogue: pf0 = silu(pf0) * (h @ w1)
        mma_gemm<6><<<dim3(FF_/128, T_/128), 256, GSMEM_BYTES>>>(
            ph, w1 + (size_t)i*D_*FF_, pf0, pf0, D_, D_, FF_, FF_,
            nullptr, nullptr, nullptr, nullptr);
        mma_gemm<1><<<dim3(D_/128, T_/128), 256, GSMEM_BYTES>>>(
            pf0, w2 + (size_t)i*FF_*D_, px, px, FF_, FF_, D_, D_,
            nullptr, nullptr, nullptr, nullptr);
    }

    rmsnorm_kernel<<<T_, 256>>>(px, on, out);
}